// round 1
// baseline (speedup 1.0000x reference)
#include <cuda_runtime.h>
#include <math.h>
#include <stdint.h>

// ----------------------------------------------------------------------------
// Model constants
// ----------------------------------------------------------------------------
constexpr int B_    = 2;
constexpr int S_    = 2048;
constexpr int T_    = B_ * S_;        // 4096 tokens
constexpr int H_    = 2048;
constexpr int NH_   = 16;
constexpr int NKV_  = 8;
constexpr int HD_   = 128;
constexpr int I_    = 5632;
constexpr int L_    = 2;
constexpr int VOCAB_= 32000;
constexpr int QKVN_ = (NH_ + 2 * NKV_) * HD_;  // 4096
constexpr int KOFF_ = NH_ * HD_;               // 2048
constexpr int VOFF_ = KOFF_ + NKV_ * HD_;      // 3072

// ----------------------------------------------------------------------------
// Scratch (device globals: allocation-free rule)
// ----------------------------------------------------------------------------
__device__ float g_h   [(size_t)T_ * H_];        // hidden / residual  (32 MB)
__device__ float g_x   [(size_t)T_ * H_];        // normed input       (32 MB)
__device__ float g_qkv [(size_t)T_ * QKVN_];     // qkv projection     (64 MB)
__device__ float g_attn[(size_t)T_ * H_];        // attn out           (32 MB)
__device__ float g_gu  [(size_t)T_ * 2 * I_];    // gate|up            (176 MB)
__device__ float g_si  [(size_t)T_ * I_];        // silu(gate)*up      (88 MB)
__device__ float g_sc  [(size_t)B_ * NH_ * S_ * S_]; // scores/probs   (512 MB)

// ----------------------------------------------------------------------------
// Generic SGEMM: C[M,N] = A[M,K] @ B[K,N] (+ R), all row-major, dims divide tiles
// BM=BN=128, BK=16, 256 threads, 8x8 per-thread tile.
// ----------------------------------------------------------------------------
template<bool RES>
__global__ __launch_bounds__(256)
void sgemm_kernel(const float* __restrict__ A, const float* __restrict__ Bm,
                  const float* __restrict__ R, float* __restrict__ C,
                  int M, int N, int K)
{
    constexpr int BM = 128, BN = 128, BK = 16, TM = 8, TN = 8;
    __shared__ float As[BK][BM];
    __shared__ float Bs[BK][BN];

    const int tid = threadIdx.x;
    const int bx = blockIdx.x, by = blockIdx.y;
    const int trow = (tid / 16) * TM;
    const int tcol = (tid % 16) * TN;

    const float* Ab = A  + (size_t)by * BM * K;
    const float* Bb = Bm + (size_t)bx * BN;

    float acc[TM][TN];
#pragma unroll
    for (int i = 0; i < TM; i++)
#pragma unroll
        for (int j = 0; j < TN; j++) acc[i][j] = 0.f;

    const int aRow = tid >> 2;          // 0..63
    const int aCol = (tid & 3) * 4;     // 0,4,8,12
    const int bRow = tid >> 5;          // 0..7
    const int bCol = (tid & 31) * 4;    // 0..124

    for (int kt = 0; kt < K; kt += BK) {
#pragma unroll
        for (int p = 0; p < 2; p++) {
            int r = aRow + p * 64;
            float4 v = *(const float4*)(Ab + (size_t)r * K + kt + aCol);
            As[aCol + 0][r] = v.x; As[aCol + 1][r] = v.y;
            As[aCol + 2][r] = v.z; As[aCol + 3][r] = v.w;
        }
#pragma unroll
        for (int p = 0; p < 2; p++) {
            int r = bRow + p * 8;
            float4 v = *(const float4*)(Bb + (size_t)(kt + r) * N + bCol);
            *(float4*)&Bs[r][bCol] = v;
        }
        __syncthreads();
#pragma unroll
        for (int k = 0; k < BK; k++) {
            float a[TM], bv[TN];
#pragma unroll
            for (int i = 0; i < TM; i++) a[i] = As[k][trow + i];
#pragma unroll
            for (int j = 0; j < TN; j++) bv[j] = Bs[k][tcol + j];
#pragma unroll
            for (int i = 0; i < TM; i++)
#pragma unroll
                for (int j = 0; j < TN; j++)
                    acc[i][j] = fmaf(a[i], bv[j], acc[i][j]);
        }
        __syncthreads();
    }

#pragma unroll
    for (int i = 0; i < TM; i++) {
        size_t row = (size_t)(by * BM + trow + i);
#pragma unroll
        for (int j = 0; j < TN; j += 4) {
            size_t idx = row * N + bx * BN + tcol + j;
            float4 o;
            o.x = acc[i][j]; o.y = acc[i][j+1]; o.z = acc[i][j+2]; o.w = acc[i][j+3];
            if (RES) {
                float4 r = *(const float4*)(R + idx);
                o.x += r.x; o.y += r.y; o.z += r.z; o.w += r.w;
            }
            *(float4*)(C + idx) = o;
        }
    }
}

// ----------------------------------------------------------------------------
// Embedding gather
// ----------------------------------------------------------------------------
__global__ void embed_kernel(const int* __restrict__ ids,
                             const float* __restrict__ emb,
                             float* __restrict__ h)
{
    int t = blockIdx.x;
    int id = ids[t];
    const float4* src = (const float4*)(emb + (size_t)id * H_);
    float4* dst = (float4*)(h + (size_t)t * H_);
    for (int i = threadIdx.x; i < H_ / 4; i += blockDim.x) dst[i] = src[i];
}

// ----------------------------------------------------------------------------
// RMSNorm: one block per token
// ----------------------------------------------------------------------------
__global__ void rmsnorm_kernel(const float* __restrict__ h,
                               const float* __restrict__ w,
                               float* __restrict__ x)
{
    int t = blockIdx.x;
    const float* hr = h + (size_t)t * H_;
    float* xr = x + (size_t)t * H_;
    __shared__ float red[256];
    float s = 0.f;
    for (int i = threadIdx.x; i < H_; i += 256) { float v = hr[i]; s += v * v; }
    red[threadIdx.x] = s; __syncthreads();
    for (int st = 128; st > 0; st >>= 1) {
        if (threadIdx.x < st) red[threadIdx.x] += red[threadIdx.x + st];
        __syncthreads();
    }
    float scale = rsqrtf(red[0] / (float)H_ + 1e-5f);
    for (int i = threadIdx.x; i < H_; i += 256) xr[i] = hr[i] * scale * w[i];
}

// ----------------------------------------------------------------------------
// RoPE: in-place on q (16 heads) + k (8 heads) inside qkv
// ----------------------------------------------------------------------------
__global__ void rope_kernel(float* __restrict__ qkv, const int* __restrict__ pos)
{
    int idx = blockIdx.x * blockDim.x + threadIdx.x;
    if (idx >= T_ * 24 * 64) return;
    int i    = idx & 63;
    int head = (idx >> 6) % 24;
    int t    = idx / (24 * 64);
    float p = (float)pos[t];
    // inv_freq = 10000^(-2i/128)
    float e = ((float)i / 64.0f) * 13.28771237954945f;  // log2(10000)
    float inv = exp2f(-e);
    float ang = p * inv;
    float sn, cs;
    sincosf(ang, &sn, &cs);
    int off = (head < NH_) ? head * HD_ : KOFF_ + (head - NH_) * HD_;
    float* v = qkv + (size_t)t * QKVN_ + off;
    float x1 = v[i], x2 = v[i + 64];
    v[i]      = x1 * cs - x2 * sn;
    v[i + 64] = x2 * cs + x1 * sn;
}

// ----------------------------------------------------------------------------
// QK^T scores: grid (kTile, qTile, b*NH). 64x64 tile, K=128 in chunks of 32.
// Skips fully-masked tiles (kTile > qTile).
// ----------------------------------------------------------------------------
__global__ __launch_bounds__(256)
void qk_kernel(const float* __restrict__ qkv, float* __restrict__ scores)
{
    const int kt = blockIdx.x, qt = blockIdx.y;
    if (kt > qt) return;
    const int z = blockIdx.z;
    const int b = z >> 4, hq = z & 15, hkv = hq >> 1;

    const float* Qb = qkv + (size_t)b * S_ * QKVN_ + (size_t)qt * 64 * QKVN_ + hq * HD_;
    const float* Kb = qkv + (size_t)b * S_ * QKVN_ + (size_t)kt * 64 * QKVN_ + KOFF_ + hkv * HD_;

    __shared__ float Qs[32][64];
    __shared__ float Ks[32][64];
    const int tid = threadIdx.x;
    const int trow = (tid / 16) * 4, tcol = (tid % 16) * 4;
    float acc[4][4] = {};

    const int lRow = tid >> 3;         // 0..31
    const int lCol = (tid & 7) * 4;    // 0..28

    for (int kk = 0; kk < HD_; kk += 32) {
#pragma unroll
        for (int p = 0; p < 2; p++) {
            int r = lRow + p * 32;
            float4 q4 = *(const float4*)(Qb + (size_t)r * QKVN_ + kk + lCol);
            Qs[lCol+0][r] = q4.x; Qs[lCol+1][r] = q4.y; Qs[lCol+2][r] = q4.z; Qs[lCol+3][r] = q4.w;
            float4 k4 = *(const float4*)(Kb + (size_t)r * QKVN_ + kk + lCol);
            Ks[lCol+0][r] = k4.x; Ks[lCol+1][r] = k4.y; Ks[lCol+2][r] = k4.z; Ks[lCol+3][r] = k4.w;
        }
        __syncthreads();
#pragma unroll
        for (int k = 0; k < 32; k++) {
            float a[4], bv[4];
#pragma unroll
            for (int i = 0; i < 4; i++) a[i]  = Qs[k][trow + i];
#pragma unroll
            for (int j = 0; j < 4; j++) bv[j] = Ks[k][tcol + j];
#pragma unroll
            for (int i = 0; i < 4; i++)
#pragma unroll
                for (int j = 0; j < 4; j++)
                    acc[i][j] = fmaf(a[i], bv[j], acc[i][j]);
        }
        __syncthreads();
    }

    const float scale = 0.08838834764831845f;  // 128^-0.5
    float* out = scores + ((size_t)z * S_ + qt * 64) * S_ + kt * 64;
#pragma unroll
    for (int i = 0; i < 4; i++)
#pragma unroll
        for (int j = 0; j < 4; j++)
            out[(size_t)(trow + i) * S_ + tcol + j] = acc[i][j] * scale;
}

// ----------------------------------------------------------------------------
// Causal softmax, in-place; zeroes masked tail so PV can run dense.
// grid (q, z), 256 threads
// ----------------------------------------------------------------------------
__global__ void softmax_kernel(float* __restrict__ scores)
{
    const int q = blockIdx.x;
    const int z = blockIdx.y;
    float* row = scores + ((size_t)z * S_ + q) * S_;
    const int n = q + 1;
    __shared__ float red[256];
    const int tid = threadIdx.x;

    float m = -1e30f;
    for (int i = tid; i < n; i += 256) m = fmaxf(m, row[i]);
    red[tid] = m; __syncthreads();
    for (int st = 128; st > 0; st >>= 1) {
        if (tid < st) red[tid] = fmaxf(red[tid], red[tid + st]);
        __syncthreads();
    }
    m = red[0]; __syncthreads();

    float s = 0.f;
    for (int i = tid; i < n; i += 256) s += expf(row[i] - m);
    red[tid] = s; __syncthreads();
    for (int st = 128; st > 0; st >>= 1) {
        if (tid < st) red[tid] += red[tid + st];
        __syncthreads();
    }
    float inv = 1.f / red[0];

    for (int i = tid; i < n; i += 256) row[i] = expf(row[i] - m) * inv;
    for (int i = n + tid; i < S_; i += 256) row[i] = 0.f;
}

// ----------------------------------------------------------------------------
// P @ V: grid (qTile, b*NH). 64 q rows x 128 d cols, K over valid keys.
// ----------------------------------------------------------------------------
__global__ __launch_bounds__(256)
void pv_kernel(const float* __restrict__ probs, const float* __restrict__ qkv,
               float* __restrict__ attn)
{
    const int qt = blockIdx.x;
    const int z  = blockIdx.y;
    const int b = z >> 4, hq = z & 15, hkv = hq >> 1;

    __shared__ float Ps[32][64];
    __shared__ float Vs[32][128];
    const int tid = threadIdx.x;
    const int trow = (tid / 16) * 4;
    const int tcol = (tid % 16) * 8;
    float acc[4][8] = {};

    const float* Prow = probs + ((size_t)z * S_ + qt * 64) * S_;
    const float* Vb   = qkv + (size_t)b * S_ * QKVN_ + VOFF_ + hkv * HD_;
    const int nk = (qt + 1) * 64;

    const int pRow = tid >> 3, pCol = (tid & 7) * 4;
    const int vRow = tid >> 5, vCol = (tid & 31) * 4;

    for (int k0 = 0; k0 < nk; k0 += 32) {
#pragma unroll
        for (int p = 0; p < 2; p++) {
            int r = pRow + p * 32;
            float4 v = *(const float4*)(Prow + (size_t)r * S_ + k0 + pCol);
            Ps[pCol+0][r] = v.x; Ps[pCol+1][r] = v.y; Ps[pCol+2][r] = v.z; Ps[pCol+3][r] = v.w;
        }
#pragma unroll
        for (int p = 0; p < 4; p++) {
            int r = vRow + p * 8;
            float4 v = *(const float4*)(Vb + (size_t)(k0 + r) * QKVN_ + vCol);
            *(float4*)&Vs[r][vCol] = v;
        }
        __syncthreads();
#pragma unroll
        for (int k = 0; k < 32; k++) {
            float a[4], bv[8];
#pragma unroll
            for (int i = 0; i < 4; i++) a[i]  = Ps[k][trow + i];
#pragma unroll
            for (int j = 0; j < 8; j++) bv[j] = Vs[k][tcol + j];
#pragma unroll
            for (int i = 0; i < 4; i++)
#pragma unroll
                for (int j = 0; j < 8; j++)
                    acc[i][j] = fmaf(a[i], bv[j], acc[i][j]);
        }
        __syncthreads();
    }

    float* ob = attn + ((size_t)(b * S_ + qt * 64)) * H_ + hq * HD_;
#pragma unroll
    for (int i = 0; i < 4; i++)
#pragma unroll
        for (int j = 0; j < 8; j += 4) {
            float4 o;
            o.x = acc[i][j]; o.y = acc[i][j+1]; o.z = acc[i][j+2]; o.w = acc[i][j+3];
            *(float4*)(ob + (size_t)(trow + i) * H_ + tcol + j) = o;
        }
}

// ----------------------------------------------------------------------------
// SiLU(gate) * up
// ----------------------------------------------------------------------------
__global__ void silu_kernel(const float* __restrict__ gu, float* __restrict__ out)
{
    size_t idx = (size_t)blockIdx.x * blockDim.x + threadIdx.x;
    if (idx >= (size_t)T_ * I_) return;
    size_t t = idx / I_, i = idx % I_;
    const float* r = gu + t * (size_t)(2 * I_);
    float g = r[i];
    float u = r[I_ + i];
    out[idx] = g / (1.f + expf(-g)) * u;
}

// ----------------------------------------------------------------------------
// Host orchestration
// ----------------------------------------------------------------------------
static void run_gemm(const float* A, const float* Bm, const float* R, float* C,
                     int M, int N, int K)
{
    dim3 grid(N / 128, M / 128);
    if (R) sgemm_kernel<true ><<<grid, 256>>>(A, Bm, R, C, M, N, K);
    else   sgemm_kernel<false><<<grid, 256>>>(A, Bm, nullptr, C, M, N, K);
}

extern "C" void kernel_launch(void* const* d_in, const int* in_sizes, int n_in,
                              void* d_out, int out_size)
{
    (void)in_sizes; (void)n_in; (void)out_size;
    const int*   ids    = (const int*)  d_in[0];
    const int*   pos    = (const int*)  d_in[1];
    const float* emb    = (const float*)d_in[2];
    const float* Wqkv   = (const float*)d_in[3];
    const float* Wo     = (const float*)d_in[4];
    const float* Wgu    = (const float*)d_in[5];
    const float* Wdn    = (const float*)d_in[6];
    const float* ln1    = (const float*)d_in[7];
    const float* ln2    = (const float*)d_in[8];
    const float* normw  = (const float*)d_in[9];
    const float* lmhead = (const float*)d_in[10];
    float* out = (float*)d_out;

    float *h, *x, *qkv, *attn, *gu, *si, *sc;
    cudaGetSymbolAddress((void**)&h,    g_h);
    cudaGetSymbolAddress((void**)&x,    g_x);
    cudaGetSymbolAddress((void**)&qkv,  g_qkv);
    cudaGetSymbolAddress((void**)&attn, g_attn);
    cudaGetSymbolAddress((void**)&gu,   g_gu);
    cudaGetSymbolAddress((void**)&si,   g_si);
    cudaGetSymbolAddress((void**)&sc,   g_sc);

    embed_kernel<<<T_, 256>>>(ids, emb, h);

    for (int l = 0; l < L_; l++) {
        const float* wqkv = Wqkv + (size_t)l * H_ * QKVN_;
        const float* wo   = Wo   + (size_t)l * H_ * H_;
        const float* wgu  = Wgu  + (size_t)l * H_ * (2 * I_);
        const float* wdn  = Wdn  + (size_t)l * I_ * H_;

        // attention block
        rmsnorm_kernel<<<T_, 256>>>(h, ln1 + (size_t)l * H_, x);
        run_gemm(x, wqkv, nullptr, qkv, T_, QKVN_, H_);
        {
            int tot = T_ * 24 * 64;
            rope_kernel<<<(tot + 255) / 256, 256>>>(qkv, pos);
        }
        qk_kernel<<<dim3(S_ / 64, S_ / 64, B_ * NH_), 256>>>(qkv, sc);
        softmax_kernel<<<dim3(S_, B_ * NH_), 256>>>(sc);
        pv_kernel<<<dim3(S_ / 64, B_ * NH_), 256>>>(sc, qkv, attn);
        run_gemm(attn, wo, h, h, T_, H_, H_);   // + residual, in-place

        // MLP block
        rmsnorm_kernel<<<T_, 256>>>(h, ln2 + (size_t)l * H_, x);
        run_gemm(x, wgu, nullptr, gu, T_, 2 * I_, H_);
        {
            size_t tot = (size_t)T_ * I_;
            silu_kernel<<<(int)((tot + 255) / 256), 256>>>(gu, si);
        }
        run_gemm(si, wdn, h, h, T_, H_, I_);    // + residual, in-place
    }

    // final norm + lm_head
    rmsnorm_kernel<<<T_, 256>>>(h, normw, x);
    run_gemm(x, lmhead, nullptr, out, T_, VOCAB_, H_);
}

// round 3
// speedup vs baseline: 1.5625x; 1.5625x over previous
#include <cuda_runtime.h>
#include <math.h>
#include <stdint.h>

// ----------------------------------------------------------------------------
// Model constants
// ----------------------------------------------------------------------------
constexpr int B_    = 2;
constexpr int S_    = 2048;
constexpr int T_    = B_ * S_;        // 4096 tokens
constexpr int H_    = 2048;
constexpr int NH_   = 16;
constexpr int NKV_  = 8;
constexpr int HD_   = 128;
constexpr int I_    = 5632;
constexpr int L_    = 2;
constexpr int VOCAB_= 32000;
constexpr int QKVN_ = (NH_ + 2 * NKV_) * HD_;  // 4096
constexpr int KOFF_ = NH_ * HD_;               // 2048
constexpr int VOFF_ = KOFF_ + NKV_ * HD_;      // 3072

// ----------------------------------------------------------------------------
// Scratch (device globals: allocation-free rule)
// ----------------------------------------------------------------------------
__device__ float g_h    [(size_t)T_ * H_];
__device__ float g_x    [(size_t)T_ * H_];      // hi
__device__ float g_xl   [(size_t)T_ * H_];      // lo
__device__ float g_qkv  [(size_t)T_ * QKVN_];
__device__ float g_attn [(size_t)T_ * H_];      // hi
__device__ float g_attnl[(size_t)T_ * H_];      // lo
__device__ float g_gu   [(size_t)T_ * 2 * I_];
__device__ float g_si   [(size_t)T_ * I_];      // hi
__device__ float g_sil  [(size_t)T_ * I_];      // lo
__device__ float g_sc   [(size_t)B_ * NH_ * S_ * S_];
__device__ float g_wr   [(size_t)H_ * VOCAB_];  // weight hi staging
__device__ float g_wl   [(size_t)H_ * VOCAB_];  // weight lo staging

// ----------------------------------------------------------------------------
// tf32 helpers
// ----------------------------------------------------------------------------
__device__ __forceinline__ float rnd_tf32(float x) {
    uint32_t u;
    asm("cvt.rna.tf32.f32 %0, %1;" : "=r"(u) : "f"(x));
    return __uint_as_float(u);
}

__device__ __forceinline__ void split_tf32(float v, float& hi, float& lo) {
    hi = rnd_tf32(v);
    lo = rnd_tf32(v - hi);   // v - hi is exact (Sterbenz)
}

__device__ __forceinline__ void mma_tf32(float c[4],
                                         uint32_t a0, uint32_t a1, uint32_t a2, uint32_t a3,
                                         uint32_t b0, uint32_t b1)
{
    asm volatile(
        "mma.sync.aligned.m16n8k8.row.col.f32.tf32.tf32.f32 "
        "{%0,%1,%2,%3}, {%4,%5,%6,%7}, {%8,%9}, {%0,%1,%2,%3};\n"
        : "+f"(c[0]), "+f"(c[1]), "+f"(c[2]), "+f"(c[3])
        : "r"(a0), "r"(a1), "r"(a2), "r"(a3), "r"(b0), "r"(b1));
}

// ----------------------------------------------------------------------------
// cp.async helpers
// ----------------------------------------------------------------------------
__device__ __forceinline__ void cpa16(void* smem, const void* g) {
    uint32_t s = (uint32_t)__cvta_generic_to_shared(smem);
    asm volatile("cp.async.cg.shared.global [%0], [%1], 16;\n" :: "r"(s), "l"(g));
}
__device__ __forceinline__ void cp_commit() {
    asm volatile("cp.async.commit_group;\n");
}
template<int N>
__device__ __forceinline__ void cp_wait() {
    asm volatile("cp.async.wait_group %0;\n" :: "n"(N));
}

// ----------------------------------------------------------------------------
// Weight split: fp32 -> (hi, lo) tf32-valued fp32 pair
// ----------------------------------------------------------------------------
__global__ void split_kernel(const float* __restrict__ in,
                             float* __restrict__ oh, float* __restrict__ ol, int n4)
{
    int i = blockIdx.x * blockDim.x + threadIdx.x;
    if (i >= n4) return;
    float4 v = ((const float4*)in)[i];
    float4 h, l;
    split_tf32(v.x, h.x, l.x); split_tf32(v.y, h.y, l.y);
    split_tf32(v.z, h.z, l.z); split_tf32(v.w, h.w, l.w);
    ((float4*)oh)[i] = h;
    ((float4*)ol)[i] = l;
}

// ----------------------------------------------------------------------------
// 3xTF32 tensor-core GEMM: C[M,N] = A[M,K] @ B[K,N] (+ R), row-major.
// A,B given as (hi,lo) tf32-valued pairs. acc += aH*bH + aH*bL + aL*bH.
// BM=BN=128, BK=32, 256 thr, warps 2(M)x4(N), warp tile 64x32.
// cp.async double-buffered, 128KB smem, XOR-swizzled.
// ----------------------------------------------------------------------------
template<bool RES>
__global__ __launch_bounds__(256, 1)
void tgemm3_kernel(const float* __restrict__ Ah, const float* __restrict__ Al,
                   const float* __restrict__ Bh, const float* __restrict__ Bl,
                   const float* __restrict__ R, float* __restrict__ C,
                   int M, int N, int K)
{
    extern __shared__ uint32_t sm[];
    uint32_t* AsH = sm;            // [2][4096]
    uint32_t* AsL = sm + 8192;
    uint32_t* BsH = sm + 16384;
    uint32_t* BsL = sm + 24576;

    const int tid   = threadIdx.x;
    const int lane  = tid & 31;
    const int wid   = tid >> 5;
    const int warpM = wid >> 2;       // 0..1
    const int warpN = wid & 3;        // 0..3
    const int g     = lane >> 2;      // 0..7
    const int tg    = lane & 3;       // 0..3

    const int bx = blockIdx.x, by = blockIdx.y;

    const int arow = tid >> 3;        // 0..31
    const int ac4  = tid & 7;         // 0..7
    const int bkr  = tid >> 5;        // 0..7
    const int bn4  = tid & 31;        // 0..31

    const float* Agh = Ah + ((size_t)(by * 128 + arow)) * K + ac4 * 4;
    const float* Agl = Al + ((size_t)(by * 128 + arow)) * K + ac4 * 4;
    const float* Bgh = Bh + (size_t)bkr * N + (size_t)bx * 128 + bn4 * 4;
    const float* Bgl = Bl + (size_t)bkr * N + (size_t)bx * 128 + bn4 * 4;

    float acc[4][4][4];
#pragma unroll
    for (int a = 0; a < 4; a++)
#pragma unroll
        for (int b = 0; b < 4; b++)
#pragma unroll
            for (int c = 0; c < 4; c++) acc[a][b][c] = 0.f;

    const int nk = K >> 5;

    auto load_stage = [&](int kt, int buf) {
#pragma unroll
        for (int p = 0; p < 4; p++) {
            int m = arow + p * 32;
            int so = m * 32 + ((ac4 ^ (m & 7)) << 2);
            cpa16(AsH + buf * 4096 + so, Agh + (size_t)(p * 32) * K + kt * 32);
            cpa16(AsL + buf * 4096 + so, Agl + (size_t)(p * 32) * K + kt * 32);
        }
#pragma unroll
        for (int p = 0; p < 4; p++) {
            int k = bkr + p * 8;
            int so = k * 128 + ((bn4 ^ ((k & 3) << 1)) << 2);
            cpa16(BsH + buf * 4096 + so, Bgh + (size_t)(kt * 32 + p * 8) * N);
            cpa16(BsL + buf * 4096 + so, Bgl + (size_t)(kt * 32 + p * 8) * N);
        }
    };

    load_stage(0, 0);
    cp_commit();

    for (int kt = 0; kt < nk; kt++) {
        if (kt + 1 < nk) {
            load_stage(kt + 1, (kt + 1) & 1);
            cp_commit();
            cp_wait<1>();
        } else {
            cp_wait<0>();
        }
        __syncthreads();

        const uint32_t* ah = AsH + (kt & 1) * 4096;
        const uint32_t* al = AsL + (kt & 1) * 4096;
        const uint32_t* bh = BsH + (kt & 1) * 4096;
        const uint32_t* bl = BsL + (kt & 1) * 4096;

#pragma unroll
        for (int ks = 0; ks < 4; ks++) {
            uint32_t bFh[4][2], bFl[4][2], aFh[4][4], aFl[4][4];
            const int k   = ks * 8 + tg;
            const int k4a = k >> 2;
#pragma unroll
            for (int nt = 0; nt < 4; nt++) {
                int n  = warpN * 32 + nt * 8 + g;
                int n4 = n >> 2, nr = n & 3;
                int o0 = k * 128       + ((n4 ^ ((k & 3) << 1)) << 2) + nr;
                int o1 = (k + 4) * 128 + ((n4 ^ ((k & 3) << 1)) << 2) + nr;
                bFh[nt][0] = bh[o0]; bFh[nt][1] = bh[o1];
                bFl[nt][0] = bl[o0]; bFl[nt][1] = bl[o1];
            }
#pragma unroll
            for (int mt = 0; mt < 4; mt++) {
                int m0 = warpM * 64 + mt * 16 + g;
                int m1 = m0 + 8;
                int o0 = m0 * 32 + ((k4a       ^ (m0 & 7)) << 2) + tg;
                int o1 = m1 * 32 + ((k4a       ^ (m1 & 7)) << 2) + tg;
                int o2 = m0 * 32 + (((k4a + 1) ^ (m0 & 7)) << 2) + tg;
                int o3 = m1 * 32 + (((k4a + 1) ^ (m1 & 7)) << 2) + tg;
                aFh[mt][0] = ah[o0]; aFh[mt][1] = ah[o1];
                aFh[mt][2] = ah[o2]; aFh[mt][3] = ah[o3];
                aFl[mt][0] = al[o0]; aFl[mt][1] = al[o1];
                aFl[mt][2] = al[o2]; aFl[mt][3] = al[o3];
            }
#pragma unroll
            for (int mt = 0; mt < 4; mt++)
#pragma unroll
                for (int nt = 0; nt < 4; nt++) {
                    mma_tf32(acc[mt][nt], aFh[mt][0], aFh[mt][1], aFh[mt][2], aFh[mt][3],
                             bFh[nt][0], bFh[nt][1]);
                    mma_tf32(acc[mt][nt], aFh[mt][0], aFh[mt][1], aFh[mt][2], aFh[mt][3],
                             bFl[nt][0], bFl[nt][1]);
                    mma_tf32(acc[mt][nt], aFl[mt][0], aFl[mt][1], aFl[mt][2], aFl[mt][3],
                             bFh[nt][0], bFh[nt][1]);
                }
        }
        __syncthreads();
    }

    // ---- epilogue ----
    const size_t rowBase = (size_t)by * 128 + warpM * 64;
    const int    colBase = bx * 128 + warpN * 32;
#pragma unroll
    for (int mt = 0; mt < 4; mt++) {
        size_t r0 = rowBase + mt * 16 + g;
#pragma unroll
        for (int nt = 0; nt < 4; nt++) {
            size_t c  = (size_t)colBase + nt * 8 + 2 * tg;
            size_t i0 = r0 * N + c;
            size_t i1 = (r0 + 8) * N + c;
            float2 v0 = make_float2(acc[mt][nt][0], acc[mt][nt][1]);
            float2 v1 = make_float2(acc[mt][nt][2], acc[mt][nt][3]);
            if (RES) {
                float2 q0 = *(const float2*)(R + i0);
                float2 q1 = *(const float2*)(R + i1);
                v0.x += q0.x; v0.y += q0.y;
                v1.x += q1.x; v1.y += q1.y;
            }
            *(float2*)(C + i0) = v0;
            *(float2*)(C + i1) = v1;
        }
    }
}

// ----------------------------------------------------------------------------
// Embedding gather
// ----------------------------------------------------------------------------
__global__ void embed_kernel(const int* __restrict__ ids,
                             const float* __restrict__ emb,
                             float* __restrict__ h)
{
    int t = blockIdx.x;
    int id = ids[t];
    const float4* src = (const float4*)(emb + (size_t)id * H_);
    float4* dst = (float4*)(h + (size_t)t * H_);
    for (int i = threadIdx.x; i < H_ / 4; i += blockDim.x) dst[i] = src[i];
}

// ----------------------------------------------------------------------------
// RMSNorm: one block per token; emits (hi, lo) pair for GEMM A side
// ----------------------------------------------------------------------------
__global__ void rmsnorm_kernel(const float* __restrict__ h,
                               const float* __restrict__ w,
                               float* __restrict__ xh, float* __restrict__ xl)
{
    int t = blockIdx.x;
    const float* hr = h + (size_t)t * H_;
    __shared__ float red[256];
    float s = 0.f;
    for (int i = threadIdx.x; i < H_; i += 256) { float v = hr[i]; s += v * v; }
    red[threadIdx.x] = s; __syncthreads();
    for (int st = 128; st > 0; st >>= 1) {
        if (threadIdx.x < st) red[threadIdx.x] += red[threadIdx.x + st];
        __syncthreads();
    }
    float scale = rsqrtf(red[0] / (float)H_ + 1e-5f);
    for (int i = threadIdx.x; i < H_; i += 256) {
        float v = hr[i] * scale * w[i];
        float hi, lo; split_tf32(v, hi, lo);
        xh[(size_t)t * H_ + i] = hi;
        xl[(size_t)t * H_ + i] = lo;
    }
}

// ----------------------------------------------------------------------------
// RoPE: in-place on q + k inside qkv
// ----------------------------------------------------------------------------
__global__ void rope_kernel(float* __restrict__ qkv, const int* __restrict__ pos)
{
    int idx = blockIdx.x * blockDim.x + threadIdx.x;
    if (idx >= T_ * 24 * 64) return;
    int i    = idx & 63;
    int head = (idx >> 6) % 24;
    int t    = idx / (24 * 64);
    float p = (float)pos[t];
    float e = ((float)i / 64.0f) * 13.28771237954945f;  // log2(10000)
    float inv = exp2f(-e);
    float ang = p * inv;
    float sn, cs;
    sincosf(ang, &sn, &cs);
    int off = (head < NH_) ? head * HD_ : KOFF_ + (head - NH_) * HD_;
    float* v = qkv + (size_t)t * QKVN_ + off;
    float x1 = v[i], x2 = v[i + 64];
    v[i]      = x1 * cs - x2 * sn;
    v[i + 64] = x2 * cs + x1 * sn;
}

// ----------------------------------------------------------------------------
// QK^T scores (fp32 SIMT, causal-tile-skipped)
// ----------------------------------------------------------------------------
__global__ __launch_bounds__(256)
void qk_kernel(const float* __restrict__ qkv, float* __restrict__ scores)
{
    const int kt = blockIdx.x, qt = blockIdx.y;
    if (kt > qt) return;
    const int z = blockIdx.z;
    const int b = z >> 4, hq = z & 15, hkv = hq >> 1;

    const float* Qb = qkv + (size_t)b * S_ * QKVN_ + (size_t)qt * 64 * QKVN_ + hq * HD_;
    const float* Kb = qkv + (size_t)b * S_ * QKVN_ + (size_t)kt * 64 * QKVN_ + KOFF_ + hkv * HD_;

    __shared__ float Qs[32][64];
    __shared__ float Ks[32][64];
    const int tid = threadIdx.x;
    const int trow = (tid / 16) * 4, tcol = (tid % 16) * 4;
    float acc[4][4] = {};

    const int lRow = tid >> 3;
    const int lCol = (tid & 7) * 4;

    for (int kk = 0; kk < HD_; kk += 32) {
#pragma unroll
        for (int p = 0; p < 2; p++) {
            int r = lRow + p * 32;
            float4 q4 = *(const float4*)(Qb + (size_t)r * QKVN_ + kk + lCol);
            Qs[lCol+0][r] = q4.x; Qs[lCol+1][r] = q4.y; Qs[lCol+2][r] = q4.z; Qs[lCol+3][r] = q4.w;
            float4 k4 = *(const float4*)(Kb + (size_t)r * QKVN_ + kk + lCol);
            Ks[lCol+0][r] = k4.x; Ks[lCol+1][r] = k4.y; Ks[lCol+2][r] = k4.z; Ks[lCol+3][r] = k4.w;
        }
        __syncthreads();
#pragma unroll
        for (int k = 0; k < 32; k++) {
            float a[4], bv[4];
#pragma unroll
            for (int i = 0; i < 4; i++) a[i]  = Qs[k][trow + i];
#pragma unroll
            for (int j = 0; j < 4; j++) bv[j] = Ks[k][tcol + j];
#pragma unroll
            for (int i = 0; i < 4; i++)
#pragma unroll
                for (int j = 0; j < 4; j++)
                    acc[i][j] = fmaf(a[i], bv[j], acc[i][j]);
        }
        __syncthreads();
    }

    const float scale = 0.08838834764831845f;
    float* out = scores + ((size_t)z * S_ + qt * 64) * S_ + kt * 64;
#pragma unroll
    for (int i = 0; i < 4; i++)
#pragma unroll
        for (int j = 0; j < 4; j++)
            out[(size_t)(trow + i) * S_ + tcol + j] = acc[i][j] * scale;
}

// ----------------------------------------------------------------------------
// Causal softmax, in-place. One __expf per element.
// ----------------------------------------------------------------------------
__global__ void softmax_kernel(float* __restrict__ scores)
{
    const int q = blockIdx.x;
    const int z = blockIdx.y;
    float* row = scores + ((size_t)z * S_ + q) * S_;
    const int n = q + 1;
    __shared__ float red[256];
    const int tid = threadIdx.x;

    float m = -1e30f;
    for (int i = tid; i < n; i += 256) m = fmaxf(m, row[i]);
    red[tid] = m; __syncthreads();
    for (int st = 128; st > 0; st >>= 1) {
        if (tid < st) red[tid] = fmaxf(red[tid], red[tid + st]);
        __syncthreads();
    }
    m = red[0]; __syncthreads();

    float s = 0.f;
    for (int i = tid; i < n; i += 256) {
        float e = __expf(row[i] - m);
        row[i] = e;
        s += e;
    }
    red[tid] = s; __syncthreads();
    for (int st = 128; st > 0; st >>= 1) {
        if (tid < st) red[tid] += red[tid + st];
        __syncthreads();
    }
    float inv = 1.f / red[0];

    for (int i = tid; i < n; i += 256) row[i] *= inv;
    for (int i = n + tid; i < S_; i += 256) row[i] = 0.f;
}

// ----------------------------------------------------------------------------
// P @ V (fp32 SIMT). Output split to (hi, lo) — feeds o-proj GEMM A.
// ----------------------------------------------------------------------------
__global__ __launch_bounds__(256)
void pv_kernel(const float* __restrict__ probs, const float* __restrict__ qkv,
               float* __restrict__ ah, float* __restrict__ al)
{
    const int qt = blockIdx.x;
    const int z  = blockIdx.y;
    const int b = z >> 4, hq = z & 15, hkv = hq >> 1;

    __shared__ float Ps[32][64];
    __shared__ float Vs[32][128];
    const int tid = threadIdx.x;
    const int trow = (tid / 16) * 4;
    const int tcol = (tid % 16) * 8;
    float acc[4][8] = {};

    const float* Prow = probs + ((size_t)z * S_ + qt * 64) * S_;
    const float* Vb   = qkv + (size_t)b * S_ * QKVN_ + VOFF_ + hkv * HD_;
    const int nk = (qt + 1) * 64;

    const int pRow = tid >> 3, pCol = (tid & 7) * 4;
    const int vRow = tid >> 5, vCol = (tid & 31) * 4;

    for (int k0 = 0; k0 < nk; k0 += 32) {
#pragma unroll
        for (int p = 0; p < 2; p++) {
            int r = pRow + p * 32;
            float4 v = *(const float4*)(Prow + (size_t)r * S_ + k0 + pCol);
            Ps[pCol+0][r] = v.x; Ps[pCol+1][r] = v.y; Ps[pCol+2][r] = v.z; Ps[pCol+3][r] = v.w;
        }
#pragma unroll
        for (int p = 0; p < 4; p++) {
            int r = vRow + p * 8;
            float4 v = *(const float4*)(Vb + (size_t)(k0 + r) * QKVN_ + vCol);
            *(float4*)&Vs[r][vCol] = v;
        }
        __syncthreads();
#pragma unroll
        for (int k = 0; k < 32; k++) {
            float a[4], bv[8];
#pragma unroll
            for (int i = 0; i < 4; i++) a[i]  = Ps[k][trow + i];
#pragma unroll
            for (int j = 0; j < 8; j++) bv[j] = Vs[k][tcol + j];
#pragma unroll
            for (int i = 0; i < 4; i++)
#pragma unroll
                for (int j = 0; j < 8; j++)
                    acc[i][j] = fmaf(a[i], bv[j], acc[i][j]);
        }
        __syncthreads();
    }

    size_t ob = ((size_t)(b * S_ + qt * 64)) * H_ + hq * HD_;
#pragma unroll
    for (int i = 0; i < 4; i++)
#pragma unroll
        for (int j = 0; j < 8; j++) {
            float hi, lo; split_tf32(acc[i][j], hi, lo);
            size_t idx = ob + (size_t)(trow + i) * H_ + tcol + j;
            ah[idx] = hi;
            al[idx] = lo;
        }
}

// ----------------------------------------------------------------------------
// SiLU(gate) * up, split to (hi, lo) — feeds down-proj GEMM A
// ----------------------------------------------------------------------------
__global__ void silu_kernel(const float* __restrict__ gu,
                            float* __restrict__ oh, float* __restrict__ ol)
{
    size_t idx = (size_t)blockIdx.x * blockDim.x + threadIdx.x;
    if (idx >= (size_t)T_ * I_) return;
    size_t t = idx / I_, i = idx % I_;
    const float* r = gu + t * (size_t)(2 * I_);
    float g = r[i];
    float u = r[I_ + i];
    float v = g / (1.f + __expf(-g)) * u;
    float hi, lo; split_tf32(v, hi, lo);
    oh[idx] = hi;
    ol[idx] = lo;
}

// ----------------------------------------------------------------------------
// Host orchestration
// ----------------------------------------------------------------------------
static void run_tgemm(const float* Ah, const float* Al,
                      const float* W, float* wh, float* wl,
                      const float* R, float* C, int M, int N, int K)
{
    int n4 = (K * N) / 4;
    split_kernel<<<(n4 + 255) / 256, 256>>>(W, wh, wl, n4);
    dim3 grid(N / 128, M / 128);
    if (R) tgemm3_kernel<true ><<<grid, 256, 131072>>>(Ah, Al, wh, wl, R, C, M, N, K);
    else   tgemm3_kernel<false><<<grid, 256, 131072>>>(Ah, Al, wh, wl, nullptr, C, M, N, K);
}

extern "C" void kernel_launch(void* const* d_in, const int* in_sizes, int n_in,
                              void* d_out, int out_size)
{
    (void)in_sizes; (void)n_in; (void)out_size;
    const int*   ids    = (const int*)  d_in[0];
    const int*   pos    = (const int*)  d_in[1];
    const float* emb    = (const float*)d_in[2];
    const float* Wqkv   = (const float*)d_in[3];
    const float* Wo     = (const float*)d_in[4];
    const float* Wgu    = (const float*)d_in[5];
    const float* Wdn    = (const float*)d_in[6];
    const float* ln1    = (const float*)d_in[7];
    const float* ln2    = (const float*)d_in[8];
    const float* normw  = (const float*)d_in[9];
    const float* lmhead = (const float*)d_in[10];
    float* out = (float*)d_out;

    cudaFuncSetAttribute(tgemm3_kernel<true>,
                         cudaFuncAttributeMaxDynamicSharedMemorySize, 131072);
    cudaFuncSetAttribute(tgemm3_kernel<false>,
                         cudaFuncAttributeMaxDynamicSharedMemorySize, 131072);

    float *h, *x, *xl, *qkv, *attn, *attnl, *gu, *si, *sil, *sc, *wh, *wl;
    cudaGetSymbolAddress((void**)&h,     g_h);
    cudaGetSymbolAddress((void**)&x,     g_x);
    cudaGetSymbolAddress((void**)&xl,    g_xl);
    cudaGetSymbolAddress((void**)&qkv,   g_qkv);
    cudaGetSymbolAddress((void**)&attn,  g_attn);
    cudaGetSymbolAddress((void**)&attnl, g_attnl);
    cudaGetSymbolAddress((void**)&gu,    g_gu);
    cudaGetSymbolAddress((void**)&si,    g_si);
    cudaGetSymbolAddress((void**)&sil,   g_sil);
    cudaGetSymbolAddress((void**)&sc,    g_sc);
    cudaGetSymbolAddress((void**)&wh,    g_wr);
    cudaGetSymbolAddress((void**)&wl,    g_wl);

    embed_kernel<<<T_, 256>>>(ids, emb, h);

    for (int l = 0; l < L_; l++) {
        const float* wqkv = Wqkv + (size_t)l * H_ * QKVN_;
        const float* wo   = Wo   + (size_t)l * H_ * H_;
        const float* wgu  = Wgu  + (size_t)l * H_ * (2 * I_);
        const float* wdn  = Wdn  + (size_t)l * I_ * H_;

        // attention block
        rmsnorm_kernel<<<T_, 256>>>(h, ln1 + (size_t)l * H_, x, xl);
        run_tgemm(x, xl, wqkv, wh, wl, nullptr, qkv, T_, QKVN_, H_);
        {
            int tot = T_ * 24 * 64;
            rope_kernel<<<(tot + 255) / 256, 256>>>(qkv, pos);
        }
        qk_kernel<<<dim3(S_ / 64, S_ / 64, B_ * NH_), 256>>>(qkv, sc);
        softmax_kernel<<<dim3(S_, B_ * NH_), 256>>>(sc);
        pv_kernel<<<dim3(S_ / 64, B_ * NH_), 256>>>(sc, qkv, attn, attnl);
        run_tgemm(attn, attnl, wo, wh, wl, h, h, T_, H_, H_);

        // MLP block
        rmsnorm_kernel<<<T_, 256>>>(h, ln2 + (size_t)l * H_, x, xl);
        run_tgemm(x, xl, wgu, wh, wl, nullptr, gu, T_, 2 * I_, H_);
        {
            size_t tot = (size_t)T_ * I_;
            silu_kernel<<<(int)((tot + 255) / 256), 256>>>(gu, si, sil);
        }
        run_tgemm(si, sil, wdn, wh, wl, h, h, T_, H_, I_);
    }

    // final norm + lm_head
    rmsnorm_kernel<<<T_, 256>>>(h, normw, x, xl);
    run_tgemm(x, xl, lmhead, wh, wl, nullptr, out, T_, VOCAB_, H_);
}

// round 4
// speedup vs baseline: 2.5995x; 1.6637x over previous
#include <cuda_runtime.h>
#include <cuda_bf16.h>
#include <math.h>
#include <stdint.h>

// ----------------------------------------------------------------------------
// Model constants
// ----------------------------------------------------------------------------
constexpr int B_    = 2;
constexpr int S_    = 2048;
constexpr int T_    = B_ * S_;        // 4096 tokens
constexpr int H_    = 2048;
constexpr int NH_   = 16;
constexpr int NKV_  = 8;
constexpr int HD_   = 128;
constexpr int I_    = 5632;
constexpr int L_    = 2;
constexpr int VOCAB_= 32000;
constexpr int QKVN_ = (NH_ + 2 * NKV_) * HD_;  // 4096
constexpr int KOFF_ = NH_ * HD_;               // 2048
constexpr int VOFF_ = KOFF_ + NKV_ * HD_;      // 3072

// ----------------------------------------------------------------------------
// Scratch (device globals: allocation-free rule)
// ----------------------------------------------------------------------------
__device__ float          g_h    [(size_t)T_ * H_];
__device__ __nv_bfloat16  g_x    [(size_t)T_ * H_];      // act hi
__device__ __nv_bfloat16  g_xl   [(size_t)T_ * H_];      // act lo
__device__ float          g_qkv  [(size_t)T_ * QKVN_];
__device__ __nv_bfloat16  g_attn [(size_t)T_ * H_];      // hi
__device__ __nv_bfloat16  g_attnl[(size_t)T_ * H_];      // lo
__device__ float          g_gu   [(size_t)T_ * 2 * I_];
__device__ __nv_bfloat16  g_si   [(size_t)T_ * I_];      // hi
__device__ __nv_bfloat16  g_sil  [(size_t)T_ * I_];      // lo
__device__ float          g_sc   [(size_t)B_ * NH_ * S_ * S_];
__device__ __nv_bfloat16  g_wh   [(size_t)H_ * VOCAB_];  // weight hi, transposed [N][K]
__device__ __nv_bfloat16  g_wl   [(size_t)H_ * VOCAB_];  // weight lo, transposed [N][K]

// ----------------------------------------------------------------------------
// bf16 split helpers
// ----------------------------------------------------------------------------
__device__ __forceinline__ void split_bf16(float v, __nv_bfloat16& hi, __nv_bfloat16& lo) {
    hi = __float2bfloat16(v);
    lo = __float2bfloat16(v - __bfloat162float(hi));
}

__device__ __forceinline__ void mma_bf16(float c[4],
                                         uint32_t a0, uint32_t a1, uint32_t a2, uint32_t a3,
                                         uint32_t b0, uint32_t b1)
{
    asm volatile(
        "mma.sync.aligned.m16n8k16.row.col.f32.bf16.bf16.f32 "
        "{%0,%1,%2,%3}, {%4,%5,%6,%7}, {%8,%9}, {%0,%1,%2,%3};\n"
        : "+f"(c[0]), "+f"(c[1]), "+f"(c[2]), "+f"(c[3])
        : "r"(a0), "r"(a1), "r"(a2), "r"(a3), "r"(b0), "r"(b1));
}

// ----------------------------------------------------------------------------
// cp.async helpers
// ----------------------------------------------------------------------------
__device__ __forceinline__ void cpa16(uint32_t* smem, const void* g) {
    uint32_t s = (uint32_t)__cvta_generic_to_shared(smem);
    asm volatile("cp.async.cg.shared.global [%0], [%1], 16;\n" :: "r"(s), "l"(g));
}
__device__ __forceinline__ void cp_commit() {
    asm volatile("cp.async.commit_group;\n");
}
template<int N>
__device__ __forceinline__ void cp_wait() {
    asm volatile("cp.async.wait_group %0;\n" :: "n"(N));
}

// ----------------------------------------------------------------------------
// Weight split + transpose: W[K][N] fp32 -> Wt_hi/Wt_lo [N][K] bf16
// ----------------------------------------------------------------------------
__global__ void wsplit_t_kernel(const float* __restrict__ W,
                                __nv_bfloat16* __restrict__ th,
                                __nv_bfloat16* __restrict__ tl,
                                int K, int N)
{
    __shared__ float tile[32][33];
    const int bx = blockIdx.x;   // along N
    const int by = blockIdx.y;   // along K
    const int tx = threadIdx.x;  // 0..31
    const int ty = threadIdx.y;  // 0..7

    const int n0 = bx * 32, k0 = by * 32;
#pragma unroll
    for (int r = ty; r < 32; r += 8)
        tile[r][tx] = W[(size_t)(k0 + r) * N + n0 + tx];
    __syncthreads();
#pragma unroll
    for (int r = ty; r < 32; r += 8) {
        float v = tile[tx][r];   // = W[k0+tx][n0+r]
        __nv_bfloat16 hi, lo; split_bf16(v, hi, lo);
        size_t idx = (size_t)(n0 + r) * K + k0 + tx;
        th[idx] = hi;
        tl[idx] = lo;
    }
}

// ----------------------------------------------------------------------------
// bf16 2-split 3-MMA GEMM: C[M,N] = A[M,K] @ B[K,N] (+ R).
// A given as hi/lo bf16 [M][K]; B given as hi/lo bf16 TRANSPOSED [N][K].
// acc += aH*bH + aH*bL + aL*bH (fp32 accumulate).
// BM=BN=128, BK=64, 256 thr, warps 2(M)x4(N), warp tile 64x32.
// cp.async double-buffered, 128KB smem, XOR-swizzled (128B rows, conflict-free).
// ----------------------------------------------------------------------------
template<bool RES>
__global__ __launch_bounds__(256, 1)
void tgemm3b_kernel(const __nv_bfloat16* __restrict__ Ah, const __nv_bfloat16* __restrict__ Al,
                    const __nv_bfloat16* __restrict__ Bh, const __nv_bfloat16* __restrict__ Bl,
                    const float* __restrict__ R, float* __restrict__ C,
                    int M, int N, int K)
{
    extern __shared__ uint32_t sm[];
    // per stage (16384 u32 = 64KB): AsH[4096] AsL[4096] BsH[4096] BsL[4096]
    const int tid   = threadIdx.x;
    const int lane  = tid & 31;
    const int wid   = tid >> 5;
    const int warpM = wid >> 2;       // 0..1
    const int warpN = wid & 3;        // 0..3
    const int g     = lane >> 2;      // 0..7
    const int tg    = lane & 3;       // 0..3

    const int bx = blockIdx.x, by = blockIdx.y;

    float acc[4][4][4];
#pragma unroll
    for (int a = 0; a < 4; a++)
#pragma unroll
        for (int b = 0; b < 4; b++)
#pragma unroll
            for (int c = 0; c < 4; c++) acc[a][b][c] = 0.f;

    const int nk = K >> 6;           // BK = 64

    // staging: 1024 16B-chunks per tile array; each thread does 4 per array
    auto load_stage = [&](int kt, int buf) {
        uint32_t* base = sm + buf * 16384;
#pragma unroll
        for (int p = 0; p < 4; p++) {
            int chunk = tid + p * 256;
            int row = chunk >> 3;        // 0..127
            int c   = chunk & 7;         // 0..7
            int so  = row * 32 + ((c ^ (row & 7)) << 2);
            const __nv_bfloat16* ag = Ah + (size_t)(by * 128 + row) * K + kt * 64 + c * 8;
            const __nv_bfloat16* al = Al + (size_t)(by * 128 + row) * K + kt * 64 + c * 8;
            const __nv_bfloat16* bg = Bh + (size_t)(bx * 128 + row) * K + kt * 64 + c * 8;
            const __nv_bfloat16* bl = Bl + (size_t)(bx * 128 + row) * K + kt * 64 + c * 8;
            cpa16(base         + so, ag);
            cpa16(base + 4096  + so, al);
            cpa16(base + 8192  + so, bg);
            cpa16(base + 12288 + so, bl);
        }
    };

    load_stage(0, 0);
    cp_commit();

    for (int kt = 0; kt < nk; kt++) {
        if (kt + 1 < nk) {
            load_stage(kt + 1, (kt + 1) & 1);
            cp_commit();
            cp_wait<1>();
        } else {
            cp_wait<0>();
        }
        __syncthreads();

        const uint32_t* ah = sm + (kt & 1) * 16384;
        const uint32_t* al = ah + 4096;
        const uint32_t* bh = ah + 8192;
        const uint32_t* bl = ah + 12288;

#pragma unroll
        for (int ks = 0; ks < 4; ks++) {     // 4 k16 steps per BK=64
            uint32_t bFh[4][2], bFl[4][2], aFh[4][4], aFl[4][4];
            const int c0 = 2 * ks, c1 = 2 * ks + 1;
#pragma unroll
            for (int nt = 0; nt < 4; nt++) {
                int n = warpN * 32 + nt * 8 + g;
                int o0 = n * 32 + ((c0 ^ (n & 7)) << 2) + tg;
                int o1 = n * 32 + ((c1 ^ (n & 7)) << 2) + tg;
                bFh[nt][0] = bh[o0]; bFh[nt][1] = bh[o1];
                bFl[nt][0] = bl[o0]; bFl[nt][1] = bl[o1];
            }
#pragma unroll
            for (int mt = 0; mt < 4; mt++) {
                int m0 = warpM * 64 + mt * 16 + g;
                int m1 = m0 + 8;
                int o0 = m0 * 32 + ((c0 ^ (m0 & 7)) << 2) + tg;
                int o1 = m1 * 32 + ((c0 ^ (m1 & 7)) << 2) + tg;
                int o2 = m0 * 32 + ((c1 ^ (m0 & 7)) << 2) + tg;
                int o3 = m1 * 32 + ((c1 ^ (m1 & 7)) << 2) + tg;
                aFh[mt][0] = ah[o0]; aFh[mt][1] = ah[o1];
                aFh[mt][2] = ah[o2]; aFh[mt][3] = ah[o3];
                aFl[mt][0] = al[o0]; aFl[mt][1] = al[o1];
                aFl[mt][2] = al[o2]; aFl[mt][3] = al[o3];
            }
#pragma unroll
            for (int mt = 0; mt < 4; mt++)
#pragma unroll
                for (int nt = 0; nt < 4; nt++) {
                    mma_bf16(acc[mt][nt], aFh[mt][0], aFh[mt][1], aFh[mt][2], aFh[mt][3],
                             bFh[nt][0], bFh[nt][1]);
                    mma_bf16(acc[mt][nt], aFh[mt][0], aFh[mt][1], aFh[mt][2], aFh[mt][3],
                             bFl[nt][0], bFl[nt][1]);
                    mma_bf16(acc[mt][nt], aFl[mt][0], aFl[mt][1], aFl[mt][2], aFl[mt][3],
                             bFh[nt][0], bFh[nt][1]);
                }
        }
        __syncthreads();
    }

    // ---- epilogue ----
    const size_t rowBase = (size_t)by * 128 + warpM * 64;
    const int    colBase = bx * 128 + warpN * 32;
#pragma unroll
    for (int mt = 0; mt < 4; mt++) {
        size_t r0 = rowBase + mt * 16 + g;
#pragma unroll
        for (int nt = 0; nt < 4; nt++) {
            size_t c  = (size_t)colBase + nt * 8 + 2 * tg;
            size_t i0 = r0 * N + c;
            size_t i1 = (r0 + 8) * N + c;
            float2 v0 = make_float2(acc[mt][nt][0], acc[mt][nt][1]);
            float2 v1 = make_float2(acc[mt][nt][2], acc[mt][nt][3]);
            if (RES) {
                float2 q0 = *(const float2*)(R + i0);
                float2 q1 = *(const float2*)(R + i1);
                v0.x += q0.x; v0.y += q0.y;
                v1.x += q1.x; v1.y += q1.y;
            }
            *(float2*)(C + i0) = v0;
            *(float2*)(C + i1) = v1;
        }
    }
}

// ----------------------------------------------------------------------------
// Embedding gather
// ----------------------------------------------------------------------------
__global__ void embed_kernel(const int* __restrict__ ids,
                             const float* __restrict__ emb,
                             float* __restrict__ h)
{
    int t = blockIdx.x;
    int id = ids[t];
    const float4* src = (const float4*)(emb + (size_t)id * H_);
    float4* dst = (float4*)(h + (size_t)t * H_);
    for (int i = threadIdx.x; i < H_ / 4; i += blockDim.x) dst[i] = src[i];
}

// ----------------------------------------------------------------------------
// RMSNorm: one block per token; emits bf16 (hi, lo) pair for GEMM A side
// ----------------------------------------------------------------------------
__global__ void rmsnorm_kernel(const float* __restrict__ h,
                               const float* __restrict__ w,
                               __nv_bfloat16* __restrict__ xh,
                               __nv_bfloat16* __restrict__ xl)
{
    int t = blockIdx.x;
    const float* hr = h + (size_t)t * H_;
    __shared__ float red[256];
    float s = 0.f;
    for (int i = threadIdx.x; i < H_; i += 256) { float v = hr[i]; s += v * v; }
    red[threadIdx.x] = s; __syncthreads();
    for (int st = 128; st > 0; st >>= 1) {
        if (threadIdx.x < st) red[threadIdx.x] += red[threadIdx.x + st];
        __syncthreads();
    }
    float scale = rsqrtf(red[0] / (float)H_ + 1e-5f);
    for (int i = threadIdx.x; i < H_; i += 256) {
        float v = hr[i] * scale * w[i];
        __nv_bfloat16 hi, lo; split_bf16(v, hi, lo);
        xh[(size_t)t * H_ + i] = hi;
        xl[(size_t)t * H_ + i] = lo;
    }
}

// ----------------------------------------------------------------------------
// RoPE: in-place on q + k inside qkv (fp32)
// ----------------------------------------------------------------------------
__global__ void rope_kernel(float* __restrict__ qkv, const int* __restrict__ pos)
{
    int idx = blockIdx.x * blockDim.x + threadIdx.x;
    if (idx >= T_ * 24 * 64) return;
    int i    = idx & 63;
    int head = (idx >> 6) % 24;
    int t    = idx / (24 * 64);
    float p = (float)pos[t];
    float e = ((float)i / 64.0f) * 13.28771237954945f;  // log2(10000)
    float inv = exp2f(-e);
    float ang = p * inv;
    float sn, cs;
    sincosf(ang, &sn, &cs);
    int off = (head < NH_) ? head * HD_ : KOFF_ + (head - NH_) * HD_;
    float* v = qkv + (size_t)t * QKVN_ + off;
    float x1 = v[i], x2 = v[i + 64];
    v[i]      = x1 * cs - x2 * sn;
    v[i + 64] = x2 * cs + x1 * sn;
}

// ----------------------------------------------------------------------------
// QK^T scores (fp32 SIMT, causal-tile-skipped)
// ----------------------------------------------------------------------------
__global__ __launch_bounds__(256)
void qk_kernel(const float* __restrict__ qkv, float* __restrict__ scores)
{
    const int kt = blockIdx.x, qt = blockIdx.y;
    if (kt > qt) return;
    const int z = blockIdx.z;
    const int b = z >> 4, hq = z & 15, hkv = hq >> 1;

    const float* Qb = qkv + (size_t)b * S_ * QKVN_ + (size_t)qt * 64 * QKVN_ + hq * HD_;
    const float* Kb = qkv + (size_t)b * S_ * QKVN_ + (size_t)kt * 64 * QKVN_ + KOFF_ + hkv * HD_;

    __shared__ float Qs[32][64];
    __shared__ float Ks[32][64];
    const int tid = threadIdx.x;
    const int trow = (tid / 16) * 4, tcol = (tid % 16) * 4;
    float acc[4][4] = {};

    const int lRow = tid >> 3;
    const int lCol = (tid & 7) * 4;

    for (int kk = 0; kk < HD_; kk += 32) {
#pragma unroll
        for (int p = 0; p < 2; p++) {
            int r = lRow + p * 32;
            float4 q4 = *(const float4*)(Qb + (size_t)r * QKVN_ + kk + lCol);
            Qs[lCol+0][r] = q4.x; Qs[lCol+1][r] = q4.y; Qs[lCol+2][r] = q4.z; Qs[lCol+3][r] = q4.w;
            float4 k4 = *(const float4*)(Kb + (size_t)r * QKVN_ + kk + lCol);
            Ks[lCol+0][r] = k4.x; Ks[lCol+1][r] = k4.y; Ks[lCol+2][r] = k4.z; Ks[lCol+3][r] = k4.w;
        }
        __syncthreads();
#pragma unroll
        for (int k = 0; k < 32; k++) {
            float a[4], bv[4];
#pragma unroll
            for (int i = 0; i < 4; i++) a[i]  = Qs[k][trow + i];
#pragma unroll
            for (int j = 0; j < 4; j++) bv[j] = Ks[k][tcol + j];
#pragma unroll
            for (int i = 0; i < 4; i++)
#pragma unroll
                for (int j = 0; j < 4; j++)
                    acc[i][j] = fmaf(a[i], bv[j], acc[i][j]);
        }
        __syncthreads();
    }

    const float scale = 0.08838834764831845f;
    float* out = scores + ((size_t)z * S_ + qt * 64) * S_ + kt * 64;
#pragma unroll
    for (int i = 0; i < 4; i++)
#pragma unroll
        for (int j = 0; j < 4; j++)
            out[(size_t)(trow + i) * S_ + tcol + j] = acc[i][j] * scale;
}

// ----------------------------------------------------------------------------
// Causal softmax, in-place. One __expf per element.
// ----------------------------------------------------------------------------
__global__ void softmax_kernel(float* __restrict__ scores)
{
    const int q = blockIdx.x;
    const int z = blockIdx.y;
    float* row = scores + ((size_t)z * S_ + q) * S_;
    const int n = q + 1;
    __shared__ float red[256];
    const int tid = threadIdx.x;

    float m = -1e30f;
    for (int i = tid; i < n; i += 256) m = fmaxf(m, row[i]);
    red[tid] = m; __syncthreads();
    for (int st = 128; st > 0; st >>= 1) {
        if (tid < st) red[tid] = fmaxf(red[tid], red[tid + st]);
        __syncthreads();
    }
    m = red[0]; __syncthreads();

    float s = 0.f;
    for (int i = tid; i < n; i += 256) {
        float e = __expf(row[i] - m);
        row[i] = e;
        s += e;
    }
    red[tid] = s; __syncthreads();
    for (int st = 128; st > 0; st >>= 1) {
        if (tid < st) red[tid] += red[tid + st];
        __syncthreads();
    }
    float inv = 1.f / red[0];

    for (int i = tid; i < n; i += 256) row[i] *= inv;
    for (int i = n + tid; i < S_; i += 256) row[i] = 0.f;
}

// ----------------------------------------------------------------------------
// P @ V (fp32 SIMT). Output split to bf16 (hi, lo) — feeds o-proj GEMM A.
// ----------------------------------------------------------------------------
__global__ __launch_bounds__(256)
void pv_kernel(const float* __restrict__ probs, const float* __restrict__ qkv,
               __nv_bfloat16* __restrict__ ah, __nv_bfloat16* __restrict__ al)
{
    const int qt = blockIdx.x;
    const int z  = blockIdx.y;
    const int b = z >> 4, hq = z & 15, hkv = hq >> 1;

    __shared__ float Ps[32][64];
    __shared__ float Vs[32][128];
    const int tid = threadIdx.x;
    const int trow = (tid / 16) * 4;
    const int tcol = (tid % 16) * 8;
    float acc[4][8] = {};

    const float* Prow = probs + ((size_t)z * S_ + qt * 64) * S_;
    const float* Vb   = qkv + (size_t)b * S_ * QKVN_ + VOFF_ + hkv * HD_;
    const int nk = (qt + 1) * 64;

    const int pRow = tid >> 3, pCol = (tid & 7) * 4;
    const int vRow = tid >> 5, vCol = (tid & 31) * 4;

    for (int k0 = 0; k0 < nk; k0 += 32) {
#pragma unroll
        for (int p = 0; p < 2; p++) {
            int r = pRow + p * 32;
            float4 v = *(const float4*)(Prow + (size_t)r * S_ + k0 + pCol);
            Ps[pCol+0][r] = v.x; Ps[pCol+1][r] = v.y; Ps[pCol+2][r] = v.z; Ps[pCol+3][r] = v.w;
        }
#pragma unroll
        for (int p = 0; p < 4; p++) {
            int r = vRow + p * 8;
            float4 v = *(const float4*)(Vb + (size_t)(k0 + r) * QKVN_ + vCol);
            *(float4*)&Vs[r][vCol] = v;
        }
        __syncthreads();
#pragma unroll
        for (int k = 0; k < 32; k++) {
            float a[4], bv[8];
#pragma unroll
            for (int i = 0; i < 4; i++) a[i]  = Ps[k][trow + i];
#pragma unroll
            for (int j = 0; j < 8; j++) bv[j] = Vs[k][tcol + j];
#pragma unroll
            for (int i = 0; i < 4; i++)
#pragma unroll
                for (int j = 0; j < 8; j++)
                    acc[i][j] = fmaf(a[i], bv[j], acc[i][j]);
        }
        __syncthreads();
    }

    size_t ob = ((size_t)(b * S_ + qt * 64)) * H_ + hq * HD_;
#pragma unroll
    for (int i = 0; i < 4; i++)
#pragma unroll
        for (int j = 0; j < 8; j++) {
            __nv_bfloat16 hi, lo; split_bf16(acc[i][j], hi, lo);
            size_t idx = ob + (size_t)(trow + i) * H_ + tcol + j;
            ah[idx] = hi;
            al[idx] = lo;
        }
}

// ----------------------------------------------------------------------------
// SiLU(gate) * up, split to bf16 (hi, lo) — feeds down-proj GEMM A
// ----------------------------------------------------------------------------
__global__ void silu_kernel(const float* __restrict__ gu,
                            __nv_bfloat16* __restrict__ oh,
                            __nv_bfloat16* __restrict__ ol)
{
    size_t idx = (size_t)blockIdx.x * blockDim.x + threadIdx.x;
    if (idx >= (size_t)T_ * I_) return;
    size_t t = idx / I_, i = idx % I_;
    const float* r = gu + t * (size_t)(2 * I_);
    float g = r[i];
    float u = r[I_ + i];
    float v = g / (1.f + __expf(-g)) * u;
    __nv_bfloat16 hi, lo; split_bf16(v, hi, lo);
    oh[idx] = hi;
    ol[idx] = lo;
}

// ----------------------------------------------------------------------------
// Host orchestration
// ----------------------------------------------------------------------------
static void run_tgemm(const __nv_bfloat16* Ah, const __nv_bfloat16* Al,
                      const float* W, __nv_bfloat16* wh, __nv_bfloat16* wl,
                      const float* R, float* C, int M, int N, int K)
{
    wsplit_t_kernel<<<dim3(N / 32, K / 32), dim3(32, 8)>>>(W, wh, wl, K, N);
    dim3 grid(N / 128, M / 128);
    if (R) tgemm3b_kernel<true ><<<grid, 256, 131072>>>(Ah, Al, wh, wl, R, C, M, N, K);
    else   tgemm3b_kernel<false><<<grid, 256, 131072>>>(Ah, Al, wh, wl, nullptr, C, M, N, K);
}

extern "C" void kernel_launch(void* const* d_in, const int* in_sizes, int n_in,
                              void* d_out, int out_size)
{
    (void)in_sizes; (void)n_in; (void)out_size;
    const int*   ids    = (const int*)  d_in[0];
    const int*   pos    = (const int*)  d_in[1];
    const float* emb    = (const float*)d_in[2];
    const float* Wqkv   = (const float*)d_in[3];
    const float* Wo     = (const float*)d_in[4];
    const float* Wgu    = (const float*)d_in[5];
    const float* Wdn    = (const float*)d_in[6];
    const float* ln1    = (const float*)d_in[7];
    const float* ln2    = (const float*)d_in[8];
    const float* normw  = (const float*)d_in[9];
    const float* lmhead = (const float*)d_in[10];
    float* out = (float*)d_out;

    cudaFuncSetAttribute(tgemm3b_kernel<true>,
                         cudaFuncAttributeMaxDynamicSharedMemorySize, 131072);
    cudaFuncSetAttribute(tgemm3b_kernel<false>,
                         cudaFuncAttributeMaxDynamicSharedMemorySize, 131072);

    float *h, *qkv, *gu, *sc;
    __nv_bfloat16 *x, *xl, *attn, *attnl, *si, *sil, *wh, *wl;
    cudaGetSymbolAddress((void**)&h,     g_h);
    cudaGetSymbolAddress((void**)&x,     g_x);
    cudaGetSymbolAddress((void**)&xl,    g_xl);
    cudaGetSymbolAddress((void**)&qkv,   g_qkv);
    cudaGetSymbolAddress((void**)&attn,  g_attn);
    cudaGetSymbolAddress((void**)&attnl, g_attnl);
    cudaGetSymbolAddress((void**)&gu,    g_gu);
    cudaGetSymbolAddress((void**)&si,    g_si);
    cudaGetSymbolAddress((void**)&sil,   g_sil);
    cudaGetSymbolAddress((void**)&sc,    g_sc);
    cudaGetSymbolAddress((void**)&wh,    g_wh);
    cudaGetSymbolAddress((void**)&wl,    g_wl);

    embed_kernel<<<T_, 256>>>(ids, emb, h);

    for (int l = 0; l < L_; l++) {
        const float* wqkv = Wqkv + (size_t)l * H_ * QKVN_;
        const float* wo   = Wo   + (size_t)l * H_ * H_;
        const float* wgu  = Wgu  + (size_t)l * H_ * (2 * I_);
        const float* wdn  = Wdn  + (size_t)l * I_ * H_;

        // attention block
        rmsnorm_kernel<<<T_, 256>>>(h, ln1 + (size_t)l * H_, x, xl);
        run_tgemm(x, xl, wqkv, wh, wl, nullptr, qkv, T_, QKVN_, H_);
        {
            int tot = T_ * 24 * 64;
            rope_kernel<<<(tot + 255) / 256, 256>>>(qkv, pos);
        }
        qk_kernel<<<dim3(S_ / 64, S_ / 64, B_ * NH_), 256>>>(qkv, sc);
        softmax_kernel<<<dim3(S_, B_ * NH_), 256>>>(sc);
        pv_kernel<<<dim3(S_ / 64, B_ * NH_), 256>>>(sc, qkv, attn, attnl);
        run_tgemm(attn, attnl, wo, wh, wl, h, h, T_, H_, H_);

        // MLP block
        rmsnorm_kernel<<<T_, 256>>>(h, ln2 + (size_t)l * H_, x, xl);
        run_tgemm(x, xl, wgu, wh, wl, nullptr, gu, T_, 2 * I_, H_);
        {
            size_t tot = (size_t)T_ * I_;
            silu_kernel<<<(int)((tot + 255) / 256), 256>>>(gu, si, sil);
        }
        run_tgemm(si, sil, wdn, wh, wl, h, h, T_, H_, I_);
    }

    // final norm + lm_head
    rmsnorm_kernel<<<T_, 256>>>(h, normw, x, xl);
    run_tgemm(x, xl, lmhead, wh, wl, nullptr, out, T_, VOCAB_, H_);
}

// round 5
// speedup vs baseline: 3.2896x; 1.2655x over previous
#include <cuda_runtime.h>
#include <cuda_bf16.h>
#include <math.h>
#include <stdint.h>

// ----------------------------------------------------------------------------
// Model constants
// ----------------------------------------------------------------------------
constexpr int B_    = 2;
constexpr int S_    = 2048;
constexpr int T_    = B_ * S_;        // 4096 tokens
constexpr int H_    = 2048;
constexpr int NH_   = 16;
constexpr int NKV_  = 8;
constexpr int HD_   = 128;
constexpr int I_    = 5632;
constexpr int L_    = 2;
constexpr int VOCAB_= 32000;
constexpr int QKVN_ = (NH_ + 2 * NKV_) * HD_;  // 4096
constexpr int KOFF_ = NH_ * HD_;               // 2048
constexpr int VOFF_ = KOFF_ + NKV_ * HD_;      // 3072

// ----------------------------------------------------------------------------
// Scratch (device globals: allocation-free rule)
// ----------------------------------------------------------------------------
__device__ float          g_h    [(size_t)T_ * H_];
__device__ __nv_bfloat16  g_x    [(size_t)T_ * H_];
__device__ __nv_bfloat16  g_xl   [(size_t)T_ * H_];
__device__ float          g_qkv  [(size_t)T_ * QKVN_];
__device__ __nv_bfloat16  g_attn [(size_t)T_ * H_];
__device__ __nv_bfloat16  g_attnl[(size_t)T_ * H_];
__device__ float          g_gu   [(size_t)T_ * 2 * I_];
__device__ __nv_bfloat16  g_si   [(size_t)T_ * I_];
__device__ __nv_bfloat16  g_sil  [(size_t)T_ * I_];
__device__ __nv_bfloat16  g_wh   [(size_t)H_ * VOCAB_];
__device__ __nv_bfloat16  g_wl   [(size_t)H_ * VOCAB_];
// flash-attention operands (RoPE'd, scaled, split)
__device__ __nv_bfloat16  g_qh [(size_t)B_ * NH_  * S_ * HD_];
__device__ __nv_bfloat16  g_ql [(size_t)B_ * NH_  * S_ * HD_];
__device__ __nv_bfloat16  g_kh [(size_t)B_ * NKV_ * S_ * HD_];
__device__ __nv_bfloat16  g_kl [(size_t)B_ * NKV_ * S_ * HD_];
__device__ __nv_bfloat16  g_vth[(size_t)B_ * NKV_ * HD_ * S_];  // V transposed
__device__ __nv_bfloat16  g_vtl[(size_t)B_ * NKV_ * HD_ * S_];

// ----------------------------------------------------------------------------
// helpers
// ----------------------------------------------------------------------------
__device__ __forceinline__ void split_bf16(float v, __nv_bfloat16& hi, __nv_bfloat16& lo) {
    hi = __float2bfloat16(v);
    lo = __float2bfloat16(v - __bfloat162float(hi));
}

__device__ __forceinline__ uint32_t pack_bf16x2(float x, float y) {
    __nv_bfloat162 t = __float22bfloat162_rn(make_float2(x, y));
    uint32_t u; memcpy(&u, &t, 4);
    return u;
}

__device__ __forceinline__ void mma_bf16(float c[4],
                                         uint32_t a0, uint32_t a1, uint32_t a2, uint32_t a3,
                                         uint32_t b0, uint32_t b1)
{
    asm volatile(
        "mma.sync.aligned.m16n8k16.row.col.f32.bf16.bf16.f32 "
        "{%0,%1,%2,%3}, {%4,%5,%6,%7}, {%8,%9}, {%0,%1,%2,%3};\n"
        : "+f"(c[0]), "+f"(c[1]), "+f"(c[2]), "+f"(c[3])
        : "r"(a0), "r"(a1), "r"(a2), "r"(a3), "r"(b0), "r"(b1));
}

__device__ __forceinline__ void cpa16(uint32_t* smem, const void* g) {
    uint32_t s = (uint32_t)__cvta_generic_to_shared(smem);
    asm volatile("cp.async.cg.shared.global [%0], [%1], 16;\n" :: "r"(s), "l"(g));
}
__device__ __forceinline__ void cp_commit() {
    asm volatile("cp.async.commit_group;\n");
}
template<int N>
__device__ __forceinline__ void cp_wait() {
    asm volatile("cp.async.wait_group %0;\n" :: "n"(N));
}

// ----------------------------------------------------------------------------
// Weight split + transpose: W[K][N] fp32 -> [N][K] bf16 hi/lo
// ----------------------------------------------------------------------------
__global__ void wsplit_t_kernel(const float* __restrict__ W,
                                __nv_bfloat16* __restrict__ th,
                                __nv_bfloat16* __restrict__ tl,
                                int K, int N)
{
    __shared__ float tile[32][33];
    const int n0 = blockIdx.x * 32, k0 = blockIdx.y * 32;
    const int tx = threadIdx.x, ty = threadIdx.y;
#pragma unroll
    for (int r = ty; r < 32; r += 8)
        tile[r][tx] = W[(size_t)(k0 + r) * N + n0 + tx];
    __syncthreads();
#pragma unroll
    for (int r = ty; r < 32; r += 8) {
        float v = tile[tx][r];
        __nv_bfloat16 hi, lo; split_bf16(v, hi, lo);
        size_t idx = (size_t)(n0 + r) * K + k0 + tx;
        th[idx] = hi;
        tl[idx] = lo;
    }
}

// ----------------------------------------------------------------------------
// bf16 2-split 3-MMA GEMM (unchanged from R4: tensor=73%)
// ----------------------------------------------------------------------------
template<bool RES>
__global__ __launch_bounds__(256, 1)
void tgemm3b_kernel(const __nv_bfloat16* __restrict__ Ah, const __nv_bfloat16* __restrict__ Al,
                    const __nv_bfloat16* __restrict__ Bh, const __nv_bfloat16* __restrict__ Bl,
                    const float* __restrict__ R, float* __restrict__ C,
                    int M, int N, int K)
{
    extern __shared__ uint32_t sm[];
    const int tid   = threadIdx.x;
    const int lane  = tid & 31;
    const int wid   = tid >> 5;
    const int warpM = wid >> 2;
    const int warpN = wid & 3;
    const int g     = lane >> 2;
    const int tg    = lane & 3;
    const int bx = blockIdx.x, by = blockIdx.y;

    float acc[4][4][4];
#pragma unroll
    for (int a = 0; a < 4; a++)
#pragma unroll
        for (int b = 0; b < 4; b++)
#pragma unroll
            for (int c = 0; c < 4; c++) acc[a][b][c] = 0.f;

    const int nk = K >> 6;

    auto load_stage = [&](int kt, int buf) {
        uint32_t* base = sm + buf * 16384;
#pragma unroll
        for (int p = 0; p < 4; p++) {
            int chunk = tid + p * 256;
            int row = chunk >> 3;
            int c   = chunk & 7;
            int so  = row * 32 + ((c ^ (row & 7)) << 2);
            cpa16(base         + so, Ah + (size_t)(by * 128 + row) * K + kt * 64 + c * 8);
            cpa16(base + 4096  + so, Al + (size_t)(by * 128 + row) * K + kt * 64 + c * 8);
            cpa16(base + 8192  + so, Bh + (size_t)(bx * 128 + row) * K + kt * 64 + c * 8);
            cpa16(base + 12288 + so, Bl + (size_t)(bx * 128 + row) * K + kt * 64 + c * 8);
        }
    };

    load_stage(0, 0);
    cp_commit();

    for (int kt = 0; kt < nk; kt++) {
        if (kt + 1 < nk) {
            load_stage(kt + 1, (kt + 1) & 1);
            cp_commit();
            cp_wait<1>();
        } else {
            cp_wait<0>();
        }
        __syncthreads();

        const uint32_t* ah = sm + (kt & 1) * 16384;
        const uint32_t* al = ah + 4096;
        const uint32_t* bh = ah + 8192;
        const uint32_t* bl = ah + 12288;

#pragma unroll
        for (int ks = 0; ks < 4; ks++) {
            uint32_t bFh[4][2], bFl[4][2], aFh[4][4], aFl[4][4];
            const int c0 = 2 * ks, c1 = 2 * ks + 1;
#pragma unroll
            for (int nt = 0; nt < 4; nt++) {
                int n = warpN * 32 + nt * 8 + g;
                int o0 = n * 32 + ((c0 ^ (n & 7)) << 2) + tg;
                int o1 = n * 32 + ((c1 ^ (n & 7)) << 2) + tg;
                bFh[nt][0] = bh[o0]; bFh[nt][1] = bh[o1];
                bFl[nt][0] = bl[o0]; bFl[nt][1] = bl[o1];
            }
#pragma unroll
            for (int mt = 0; mt < 4; mt++) {
                int m0 = warpM * 64 + mt * 16 + g;
                int m1 = m0 + 8;
                int o0 = m0 * 32 + ((c0 ^ (m0 & 7)) << 2) + tg;
                int o1 = m1 * 32 + ((c0 ^ (m1 & 7)) << 2) + tg;
                int o2 = m0 * 32 + ((c1 ^ (m0 & 7)) << 2) + tg;
                int o3 = m1 * 32 + ((c1 ^ (m1 & 7)) << 2) + tg;
                aFh[mt][0] = ah[o0]; aFh[mt][1] = ah[o1];
                aFh[mt][2] = ah[o2]; aFh[mt][3] = ah[o3];
                aFl[mt][0] = al[o0]; aFl[mt][1] = al[o1];
                aFl[mt][2] = al[o2]; aFl[mt][3] = al[o3];
            }
#pragma unroll
            for (int mt = 0; mt < 4; mt++)
#pragma unroll
                for (int nt = 0; nt < 4; nt++) {
                    mma_bf16(acc[mt][nt], aFh[mt][0], aFh[mt][1], aFh[mt][2], aFh[mt][3],
                             bFh[nt][0], bFh[nt][1]);
                    mma_bf16(acc[mt][nt], aFh[mt][0], aFh[mt][1], aFh[mt][2], aFh[mt][3],
                             bFl[nt][0], bFl[nt][1]);
                    mma_bf16(acc[mt][nt], aFl[mt][0], aFl[mt][1], aFl[mt][2], aFl[mt][3],
                             bFh[nt][0], bFh[nt][1]);
                }
        }
        __syncthreads();
    }

    const size_t rowBase = (size_t)by * 128 + warpM * 64;
    const int    colBase = bx * 128 + warpN * 32;
#pragma unroll
    for (int mt = 0; mt < 4; mt++) {
        size_t r0 = rowBase + mt * 16 + g;
#pragma unroll
        for (int nt = 0; nt < 4; nt++) {
            size_t c  = (size_t)colBase + nt * 8 + 2 * tg;
            size_t i0 = r0 * N + c;
            size_t i1 = (r0 + 8) * N + c;
            float2 v0 = make_float2(acc[mt][nt][0], acc[mt][nt][1]);
            float2 v1 = make_float2(acc[mt][nt][2], acc[mt][nt][3]);
            if (RES) {
                float2 q0 = *(const float2*)(R + i0);
                float2 q1 = *(const float2*)(R + i1);
                v0.x += q0.x; v0.y += q0.y;
                v1.x += q1.x; v1.y += q1.y;
            }
            *(float2*)(C + i0) = v0;
            *(float2*)(C + i1) = v1;
        }
    }
}

// ----------------------------------------------------------------------------
// Embedding gather
// ----------------------------------------------------------------------------
__global__ void embed_kernel(const int* __restrict__ ids,
                             const float* __restrict__ emb,
                             float* __restrict__ h)
{
    int t = blockIdx.x;
    int id = ids[t];
    const float4* src = (const float4*)(emb + (size_t)id * H_);
    float4* dst = (float4*)(h + (size_t)t * H_);
    for (int i = threadIdx.x; i < H_ / 4; i += blockDim.x) dst[i] = src[i];
}

// ----------------------------------------------------------------------------
// RMSNorm -> bf16 (hi, lo)
// ----------------------------------------------------------------------------
__global__ void rmsnorm_kernel(const float* __restrict__ h,
                               const float* __restrict__ w,
                               __nv_bfloat16* __restrict__ xh,
                               __nv_bfloat16* __restrict__ xl)
{
    int t = blockIdx.x;
    const float* hr = h + (size_t)t * H_;
    __shared__ float red[256];
    float s = 0.f;
    for (int i = threadIdx.x; i < H_; i += 256) { float v = hr[i]; s += v * v; }
    red[threadIdx.x] = s; __syncthreads();
    for (int st = 128; st > 0; st >>= 1) {
        if (threadIdx.x < st) red[threadIdx.x] += red[threadIdx.x + st];
        __syncthreads();
    }
    float scale = rsqrtf(red[0] / (float)H_ + 1e-5f);
    for (int i = threadIdx.x; i < H_; i += 256) {
        float v = hr[i] * scale * w[i];
        __nv_bfloat16 hi, lo; split_bf16(v, hi, lo);
        xh[(size_t)t * H_ + i] = hi;
        xl[(size_t)t * H_ + i] = lo;
    }
}

// ----------------------------------------------------------------------------
// Q/K prep: fused RoPE + (Q) 1/sqrt(HD) scale + bf16 hi/lo split.
// Q -> [B][NH][S][HD], K -> [B][NKV][S][HD]
// ----------------------------------------------------------------------------
__global__ void qkprep_kernel(const float* __restrict__ qkv, const int* __restrict__ pos,
                              __nv_bfloat16* __restrict__ Qh, __nv_bfloat16* __restrict__ Ql,
                              __nv_bfloat16* __restrict__ Kh, __nv_bfloat16* __restrict__ Kl)
{
    int idx = blockIdx.x * blockDim.x + threadIdx.x;
    if (idx >= T_ * 24 * 64) return;
    int i    = idx & 63;
    int head = (idx >> 6) % 24;
    int t    = idx / (24 * 64);
    int b = t / S_, s = t % S_;

    float p = (float)pos[t];
    float e = ((float)i / 64.0f) * 13.28771237954945f;  // log2(10000)
    float inv = exp2f(-e);
    float ang = p * inv;
    float sn, cs;
    sincosf(ang, &sn, &cs);

    int off = (head < NH_) ? head * HD_ : KOFF_ + (head - NH_) * HD_;
    const float* v = qkv + (size_t)t * QKVN_ + off;
    float x1 = v[i], x2 = v[i + 64];
    float r1 = x1 * cs - x2 * sn;
    float r2 = x2 * cs + x1 * sn;

    __nv_bfloat16 *dh, *dl;
    if (head < NH_) {
        const float scale = 0.08838834764831845f;  // 128^-0.5 folded into Q
        r1 *= scale; r2 *= scale;
        size_t base = (((size_t)(b * NH_ + head)) * S_ + s) * HD_;
        dh = Qh + base; dl = Ql + base;
    } else {
        size_t base = (((size_t)(b * NKV_ + head - NH_)) * S_ + s) * HD_;
        dh = Kh + base; dl = Kl + base;
    }
    __nv_bfloat16 h1, l1, h2, l2;
    split_bf16(r1, h1, l1);
    split_bf16(r2, h2, l2);
    dh[i] = h1;      dl[i] = l1;
    dh[i + 64] = h2; dl[i + 64] = l2;
}

// ----------------------------------------------------------------------------
// V prep: transpose to [B][NKV][HD][S] + bf16 hi/lo split
// ----------------------------------------------------------------------------
__global__ void vprep_kernel(const float* __restrict__ qkv,
                             __nv_bfloat16* __restrict__ Vth,
                             __nv_bfloat16* __restrict__ Vtl)
{
    __shared__ float tile[32][33];
    const int z = blockIdx.z;
    const int b = z / NKV_, hkv = z % NKV_;
    const int s0 = blockIdx.x * 32, d0 = blockIdx.y * 32;
    const int tx = threadIdx.x, ty = threadIdx.y;
#pragma unroll
    for (int r = ty; r < 32; r += 8)
        tile[r][tx] = qkv[(size_t)(b * S_ + s0 + r) * QKVN_ + VOFF_ + hkv * HD_ + d0 + tx];
    __syncthreads();
    size_t base = ((size_t)(b * NKV_ + hkv)) * HD_ * S_;
#pragma unroll
    for (int r = ty; r < 32; r += 8) {
        float v = tile[tx][r];   // = V[s0+tx][d0+r]
        __nv_bfloat16 hi, lo; split_bf16(v, hi, lo);
        size_t idx = base + (size_t)(d0 + r) * S_ + s0 + tx;
        Vth[idx] = hi;
        Vtl[idx] = lo;
    }
}

// ----------------------------------------------------------------------------
// Flash attention: 64 q-rows per block, 64-key tiles, bf16 hi/lo 3-MMA for
// both QK and PV, online softmax. Output split bf16 hi/lo for o-proj A.
// Block = 128 threads (4 warps), warp w owns q rows [16w, 16w+16).
// ----------------------------------------------------------------------------
__global__ __launch_bounds__(128)
void flash_kernel(const __nv_bfloat16* __restrict__ Qh, const __nv_bfloat16* __restrict__ Ql,
                  const __nv_bfloat16* __restrict__ Kh, const __nv_bfloat16* __restrict__ Kl,
                  const __nv_bfloat16* __restrict__ Vth, const __nv_bfloat16* __restrict__ Vtl,
                  __nv_bfloat16* __restrict__ Oh, __nv_bfloat16* __restrict__ Ol)
{
    extern __shared__ uint32_t sm[];
    uint32_t* KsH = sm;           // [64 keys][64 u32]  swizzled
    uint32_t* KsL = sm + 4096;
    uint32_t* VsH = sm + 8192;    // [128 hd][32 u32]  swizzled
    uint32_t* VsL = sm + 12288;

    const int qt = (int)gridDim.x - 1 - (int)blockIdx.x;   // long blocks first
    const int z  = blockIdx.y;
    const int b  = z >> 4, hq = z & 15, hkv = hq >> 1;

    const int tid  = threadIdx.x;
    const int lane = tid & 31;
    const int w    = tid >> 5;
    const int g    = lane >> 2;
    const int tg   = lane & 3;

    // ---- Q fragments: held in registers for the whole block ----
    uint32_t qFh[8][4], qFl[8][4];
    {
        const uint32_t* qbh = (const uint32_t*)(Qh + (((size_t)(b * NH_ + hq)) * S_ + qt * 64 + w * 16) * HD_);
        const uint32_t* qbl = (const uint32_t*)(Ql + (((size_t)(b * NH_ + hq)) * S_ + qt * 64 + w * 16) * HD_);
#pragma unroll
        for (int ks = 0; ks < 8; ks++) {
            int c = 8 * ks + tg;
            qFh[ks][0] = qbh[g * 64 + c];
            qFh[ks][1] = qbh[(g + 8) * 64 + c];
            qFh[ks][2] = qbh[g * 64 + c + 4];
            qFh[ks][3] = qbh[(g + 8) * 64 + c + 4];
            qFl[ks][0] = qbl[g * 64 + c];
            qFl[ks][1] = qbl[(g + 8) * 64 + c];
            qFl[ks][2] = qbl[g * 64 + c + 4];
            qFl[ks][3] = qbl[(g + 8) * 64 + c + 4];
        }
    }

    float oAcc[16][4];
#pragma unroll
    for (int i = 0; i < 16; i++)
#pragma unroll
        for (int j = 0; j < 4; j++) oAcc[i][j] = 0.f;
    float mA = -1e30f, mB = -1e30f, lA = 0.f, lB = 0.f;

    const __nv_bfloat16* KgH = Kh  + ((size_t)(b * NKV_ + hkv)) * S_ * HD_;
    const __nv_bfloat16* KgL = Kl  + ((size_t)(b * NKV_ + hkv)) * S_ * HD_;
    const __nv_bfloat16* VgH = Vth + ((size_t)(b * NKV_ + hkv)) * HD_ * S_;
    const __nv_bfloat16* VgL = Vtl + ((size_t)(b * NKV_ + hkv)) * HD_ * S_;

    for (int kt = 0; kt <= qt; kt++) {
        // ---- fill K,V tiles (cp.async, swizzled) ----
#pragma unroll
        for (int p = 0; p < 8; p++) {
            int i = tid + p * 128;
            int r = i >> 4, cc = i & 15;                       // key row, 16B chunk
            int dst = r * 64 + ((cc ^ (r & 7)) << 2);
            cpa16(KsH + dst, KgH + (size_t)(kt * 64 + r) * HD_ + cc * 8);
            cpa16(KsL + dst, KgL + (size_t)(kt * 64 + r) * HD_ + cc * 8);
        }
#pragma unroll
        for (int p = 0; p < 8; p++) {
            int i = tid + p * 128;
            int n = i >> 3, cc = i & 7;                        // hd row, 16B chunk
            int dst = n * 32 + ((cc ^ (n & 7)) << 2);
            cpa16(VsH + dst, VgH + (size_t)n * S_ + kt * 64 + cc * 8);
            cpa16(VsL + dst, VgL + (size_t)n * S_ + kt * 64 + cc * 8);
        }
        cp_commit();
        cp_wait<0>();
        __syncthreads();

        // ---- S = Q K^T (3-MMA split) ----
        float sAcc[8][4];
#pragma unroll
        for (int i = 0; i < 8; i++)
#pragma unroll
            for (int j = 0; j < 4; j++) sAcc[i][j] = 0.f;

#pragma unroll
        for (int ks = 0; ks < 8; ks++) {
            uint32_t kFh[8][2], kFl[8][2];
            const int c0 = 8 * ks + tg;
#pragma unroll
            for (int nt = 0; nt < 8; nt++) {
                int key = nt * 8 + g;
                int sw = (key & 7) << 2;
                int o0 = key * 64 + (c0 ^ sw);
                int o1 = key * 64 + ((c0 + 4) ^ sw);
                kFh[nt][0] = KsH[o0]; kFh[nt][1] = KsH[o1];
                kFl[nt][0] = KsL[o0]; kFl[nt][1] = KsL[o1];
            }
#pragma unroll
            for (int nt = 0; nt < 8; nt++) {
                mma_bf16(sAcc[nt], qFh[ks][0], qFh[ks][1], qFh[ks][2], qFh[ks][3],
                         kFh[nt][0], kFh[nt][1]);
                mma_bf16(sAcc[nt], qFh[ks][0], qFh[ks][1], qFh[ks][2], qFh[ks][3],
                         kFl[nt][0], kFl[nt][1]);
                mma_bf16(sAcc[nt], qFl[ks][0], qFl[ks][1], qFl[ks][2], qFl[ks][3],
                         kFh[nt][0], kFh[nt][1]);
            }
        }

        // ---- causal mask (diagonal tile only) ----
        if (kt == qt) {
            const int qrA = w * 16 + g, qrB = qrA + 8;
#pragma unroll
            for (int nt = 0; nt < 8; nt++) {
                int k0 = nt * 8 + 2 * tg, k1 = k0 + 1;
                if (k0 > qrA) sAcc[nt][0] = -1e30f;
                if (k1 > qrA) sAcc[nt][1] = -1e30f;
                if (k0 > qrB) sAcc[nt][2] = -1e30f;
                if (k1 > qrB) sAcc[nt][3] = -1e30f;
            }
        }

        // ---- online softmax ----
        float tmA = -1e30f, tmB = -1e30f;
#pragma unroll
        for (int nt = 0; nt < 8; nt++) {
            tmA = fmaxf(tmA, fmaxf(sAcc[nt][0], sAcc[nt][1]));
            tmB = fmaxf(tmB, fmaxf(sAcc[nt][2], sAcc[nt][3]));
        }
        tmA = fmaxf(tmA, __shfl_xor_sync(0xffffffff, tmA, 1));
        tmA = fmaxf(tmA, __shfl_xor_sync(0xffffffff, tmA, 2));
        tmB = fmaxf(tmB, __shfl_xor_sync(0xffffffff, tmB, 1));
        tmB = fmaxf(tmB, __shfl_xor_sync(0xffffffff, tmB, 2));
        float nmA = fmaxf(mA, tmA), nmB = fmaxf(mB, tmB);
        float eA = __expf(mA - nmA), eB = __expf(mB - nmB);

        float rsA = 0.f, rsB = 0.f;
#pragma unroll
        for (int nt = 0; nt < 8; nt++) {
            sAcc[nt][0] = __expf(sAcc[nt][0] - nmA);
            sAcc[nt][1] = __expf(sAcc[nt][1] - nmA);
            sAcc[nt][2] = __expf(sAcc[nt][2] - nmB);
            sAcc[nt][3] = __expf(sAcc[nt][3] - nmB);
            rsA += sAcc[nt][0] + sAcc[nt][1];
            rsB += sAcc[nt][2] + sAcc[nt][3];
        }
        rsA += __shfl_xor_sync(0xffffffff, rsA, 1);
        rsA += __shfl_xor_sync(0xffffffff, rsA, 2);
        rsB += __shfl_xor_sync(0xffffffff, rsB, 1);
        rsB += __shfl_xor_sync(0xffffffff, rsB, 2);
        lA = lA * eA + rsA;
        lB = lB * eB + rsB;
        mA = nmA; mB = nmB;
#pragma unroll
        for (int nt = 0; nt < 16; nt++) {
            oAcc[nt][0] *= eA; oAcc[nt][1] *= eA;
            oAcc[nt][2] *= eB; oAcc[nt][3] *= eB;
        }

        // ---- O += P V (3-MMA split; P frags built from sAcc registers) ----
#pragma unroll
        for (int ks2 = 0; ks2 < 4; ks2++) {
            uint32_t ph[4], pl[4];
#pragma unroll
            for (int q = 0; q < 2; q++) {         // q=0: nt 2ks2 (a0,a1); q=1: nt 2ks2+1 (a2,a3)
                const float* s4 = sAcc[2 * ks2 + q];
                uint32_t hp0 = pack_bf16x2(s4[0], s4[1]);
                uint32_t hp1 = pack_bf16x2(s4[2], s4[3]);
                float h00 = __uint_as_float(hp0 << 16);
                float h01 = __uint_as_float(hp0 & 0xFFFF0000u);
                float h10 = __uint_as_float(hp1 << 16);
                float h11 = __uint_as_float(hp1 & 0xFFFF0000u);
                ph[2 * q]     = hp0;
                ph[2 * q + 1] = hp1;
                pl[2 * q]     = pack_bf16x2(s4[0] - h00, s4[1] - h01);
                pl[2 * q + 1] = pack_bf16x2(s4[2] - h10, s4[3] - h11);
            }
            const int kp = 8 * ks2 + tg;
#pragma unroll
            for (int nt2 = 0; nt2 < 16; nt2++) {
                int n = nt2 * 8 + g;
                int sw = (n & 7) << 2;
                int o0 = n * 32 + (kp ^ sw);
                int o1 = n * 32 + ((kp + 4) ^ sw);
                uint32_t v0h = VsH[o0], v1h = VsH[o1];
                uint32_t v0l = VsL[o0], v1l = VsL[o1];
                mma_bf16(oAcc[nt2], ph[0], ph[1], ph[2], ph[3], v0h, v1h);
                mma_bf16(oAcc[nt2], ph[0], ph[1], ph[2], ph[3], v0l, v1l);
                mma_bf16(oAcc[nt2], pl[0], pl[1], pl[2], pl[3], v0h, v1h);
            }
        }
        __syncthreads();
    }

    // ---- finalize: divide by l, split hi/lo, write ----
    const float ilA = 1.f / lA, ilB = 1.f / lB;
    const size_t tA = (size_t)b * S_ + qt * 64 + w * 16 + g;
    const size_t tB = tA + 8;
#pragma unroll
    for (int nt2 = 0; nt2 < 16; nt2++) {
        int col = hq * HD_ + nt2 * 8 + 2 * tg;
        float a0 = oAcc[nt2][0] * ilA, a1 = oAcc[nt2][1] * ilA;
        float b0 = oAcc[nt2][2] * ilB, b1 = oAcc[nt2][3] * ilB;

        uint32_t ahp = pack_bf16x2(a0, a1);
        uint32_t bhp = pack_bf16x2(b0, b1);
        float ah0 = __uint_as_float(ahp << 16), ah1 = __uint_as_float(ahp & 0xFFFF0000u);
        float bh0 = __uint_as_float(bhp << 16), bh1 = __uint_as_float(bhp & 0xFFFF0000u);
        uint32_t alp = pack_bf16x2(a0 - ah0, a1 - ah1);
        uint32_t blp = pack_bf16x2(b0 - bh0, b1 - bh1);

        *(uint32_t*)(Oh + tA * H_ + col) = ahp;
        *(uint32_t*)(Ol + tA * H_ + col) = alp;
        *(uint32_t*)(Oh + tB * H_ + col) = bhp;
        *(uint32_t*)(Ol + tB * H_ + col) = blp;
    }
}

// ----------------------------------------------------------------------------
// SiLU(gate) * up -> bf16 (hi, lo)
// ----------------------------------------------------------------------------
__global__ void silu_kernel(const float* __restrict__ gu,
                            __nv_bfloat16* __restrict__ oh,
                            __nv_bfloat16* __restrict__ ol)
{
    size_t idx = (size_t)blockIdx.x * blockDim.x + threadIdx.x;
    if (idx >= (size_t)T_ * I_) return;
    size_t t = idx / I_, i = idx % I_;
    const float* r = gu + t * (size_t)(2 * I_);
    float g = r[i];
    float u = r[I_ + i];
    float v = g / (1.f + __expf(-g)) * u;
    __nv_bfloat16 hi, lo; split_bf16(v, hi, lo);
    oh[idx] = hi;
    ol[idx] = lo;
}

// ----------------------------------------------------------------------------
// Host orchestration
// ----------------------------------------------------------------------------
static void run_tgemm(const __nv_bfloat16* Ah, const __nv_bfloat16* Al,
                      const float* W, __nv_bfloat16* wh, __nv_bfloat16* wl,
                      const float* R, float* C, int M, int N, int K)
{
    wsplit_t_kernel<<<dim3(N / 32, K / 32), dim3(32, 8)>>>(W, wh, wl, K, N);
    dim3 grid(N / 128, M / 128);
    if (R) tgemm3b_kernel<true ><<<grid, 256, 131072>>>(Ah, Al, wh, wl, R, C, M, N, K);
    else   tgemm3b_kernel<false><<<grid, 256, 131072>>>(Ah, Al, wh, wl, nullptr, C, M, N, K);
}

extern "C" void kernel_launch(void* const* d_in, const int* in_sizes, int n_in,
                              void* d_out, int out_size)
{
    (void)in_sizes; (void)n_in; (void)out_size;
    const int*   ids    = (const int*)  d_in[0];
    const int*   pos    = (const int*)  d_in[1];
    const float* emb    = (const float*)d_in[2];
    const float* Wqkv   = (const float*)d_in[3];
    const float* Wo     = (const float*)d_in[4];
    const float* Wgu    = (const float*)d_in[5];
    const float* Wdn    = (const float*)d_in[6];
    const float* ln1    = (const float*)d_in[7];
    const float* ln2    = (const float*)d_in[8];
    const float* normw  = (const float*)d_in[9];
    const float* lmhead = (const float*)d_in[10];
    float* out = (float*)d_out;

    cudaFuncSetAttribute(tgemm3b_kernel<true>,
                         cudaFuncAttributeMaxDynamicSharedMemorySize, 131072);
    cudaFuncSetAttribute(tgemm3b_kernel<false>,
                         cudaFuncAttributeMaxDynamicSharedMemorySize, 131072);
    cudaFuncSetAttribute(flash_kernel,
                         cudaFuncAttributeMaxDynamicSharedMemorySize, 65536);

    float *h, *qkv, *gu;
    __nv_bfloat16 *x, *xl, *attn, *attnl, *si, *sil, *wh, *wl;
    __nv_bfloat16 *qh, *ql, *kh, *kl, *vth, *vtl;
    cudaGetSymbolAddress((void**)&h,     g_h);
    cudaGetSymbolAddress((void**)&x,     g_x);
    cudaGetSymbolAddress((void**)&xl,    g_xl);
    cudaGetSymbolAddress((void**)&qkv,   g_qkv);
    cudaGetSymbolAddress((void**)&attn,  g_attn);
    cudaGetSymbolAddress((void**)&attnl, g_attnl);
    cudaGetSymbolAddress((void**)&gu,    g_gu);
    cudaGetSymbolAddress((void**)&si,    g_si);
    cudaGetSymbolAddress((void**)&sil,   g_sil);
    cudaGetSymbolAddress((void**)&wh,    g_wh);
    cudaGetSymbolAddress((void**)&wl,    g_wl);
    cudaGetSymbolAddress((void**)&qh,    g_qh);
    cudaGetSymbolAddress((void**)&ql,    g_ql);
    cudaGetSymbolAddress((void**)&kh,    g_kh);
    cudaGetSymbolAddress((void**)&kl,    g_kl);
    cudaGetSymbolAddress((void**)&vth,   g_vth);
    cudaGetSymbolAddress((void**)&vtl,   g_vtl);

    embed_kernel<<<T_, 256>>>(ids, emb, h);

    for (int l = 0; l < L_; l++) {
        const float* wqkv = Wqkv + (size_t)l * H_ * QKVN_;
        const float* wo   = Wo   + (size_t)l * H_ * H_;
        const float* wgu  = Wgu  + (size_t)l * H_ * (2 * I_);
        const float* wdn  = Wdn  + (size_t)l * I_ * H_;

        // ---- attention block ----
        rmsnorm_kernel<<<T_, 256>>>(h, ln1 + (size_t)l * H_, x, xl);
        run_tgemm(x, xl, wqkv, wh, wl, nullptr, qkv, T_, QKVN_, H_);

        {
            int tot = T_ * 24 * 64;
            qkprep_kernel<<<(tot + 255) / 256, 256>>>(qkv, pos, qh, ql, kh, kl);
        }
        vprep_kernel<<<dim3(S_ / 32, HD_ / 32, B_ * NKV_), dim3(32, 8)>>>(qkv, vth, vtl);

        flash_kernel<<<dim3(S_ / 64, B_ * NH_), 128, 65536>>>(qh, ql, kh, kl, vth, vtl,
                                                              attn, attnl);

        run_tgemm(attn, attnl, wo, wh, wl, h, h, T_, H_, H_);

        // ---- MLP block ----
        rmsnorm_kernel<<<T_, 256>>>(h, ln2 + (size_t)l * H_, x, xl);
        run_tgemm(x, xl, wgu, wh, wl, nullptr, gu, T_, 2 * I_, H_);
        {
            size_t tot = (size_t)T_ * I_;
            silu_kernel<<<(int)((tot + 255) / 256), 256>>>(gu, si, sil);
        }
        run_tgemm(si, sil, wdn, wh, wl, h, h, T_, H_, I_);
    }

    // final norm + lm_head
    rmsnorm_kernel<<<T_, 256>>>(h, normw, x, xl);
    run_tgemm(x, xl, lmhead, wh, wl, nullptr, out, T_, VOCAB_, H_);
}